// round 1
// baseline (speedup 1.0000x reference)
#include <cuda_runtime.h>

#define S_LEN   2048
#define DMODEL  1024
#define NHEADS  16
#define HDIM    64
#define BATCH   4
#define BHCNT   (BATCH * NHEADS)          // 64
#define MROWS   (BATCH * S_LEN)           // 8192
#define HS_ELEMS (BATCH * NHEADS * S_LEN * HDIM)  // 8388608

// Scratch in head-split layout [b*16+h][s][d]
__device__ float g_Q[HS_ELEMS];
__device__ float g_K[HS_ELEMS];
__device__ float g_V[HS_ELEMS];
__device__ float g_O[HS_ELEMS];

// ---------------------------------------------------------------------------
// SGEMM: C[M=8192, N=1024] = A[8192,1024] @ W[1024,1024]
// 128x128 tile, BK=8, 256 threads, 8x8 microtile.
// GATHER_A: A is read from head-split layout  [b,h,s,d] (for final projection)
// SCATTER_C: C is written to head-split layout [b,h,s,d] (for QKV projections)
// ---------------------------------------------------------------------------
template <bool GATHER_A, bool SCATTER_C>
__global__ void __launch_bounds__(256)
gemm_kernel(const float* __restrict__ A, const float* __restrict__ W,
            float* __restrict__ C)
{
    __shared__ float As[8][132];   // padded to dodge STS bank conflicts
    __shared__ float Ws[8][128];

    const int tid = threadIdx.x;
    const int bc  = blockIdx.x;    // N tile (0..7)
    const int br  = blockIdx.y;    // M tile (0..63)
    const int tx  = tid & 15;
    const int ty  = tid >> 4;

    // A-tile load indices: 128 rows x 8 k -> 1024 floats -> 1 float4/thread
    const int arow = tid >> 1;
    const int ak   = (tid & 1) * 4;
    // W-tile load indices: 8 k x 128 n
    const int wk = tid >> 5;
    const int wn = (tid & 31) * 4;

    const int row_g = br * 128 + arow;

    float acc[8][8];
    #pragma unroll
    for (int i = 0; i < 8; i++)
        #pragma unroll
        for (int j = 0; j < 8; j++) acc[i][j] = 0.0f;

    for (int k0 = 0; k0 < DMODEL; k0 += 8) {
        const int kg = k0 + ak;
        float4 a4;
        if (GATHER_A) {
            const int b = row_g >> 11, s = row_g & 2047;
            const int h = kg >> 6,     d = kg & 63;
            a4 = *(const float4*)&A[((((b << 4) + h) * S_LEN + s) * HDIM) + d];
        } else {
            a4 = *(const float4*)&A[row_g * DMODEL + kg];
        }
        const float4 w4 = *(const float4*)&W[(k0 + wk) * DMODEL + bc * 128 + wn];

        __syncthreads();
        As[ak + 0][arow] = a4.x;
        As[ak + 1][arow] = a4.y;
        As[ak + 2][arow] = a4.z;
        As[ak + 3][arow] = a4.w;
        *(float4*)&Ws[wk][wn] = w4;
        __syncthreads();

        #pragma unroll
        for (int kk = 0; kk < 8; kk++) {
            float a[8], b[8];
            *(float4*)&a[0] = *(const float4*)&As[kk][ty * 8];
            *(float4*)&a[4] = *(const float4*)&As[kk][ty * 8 + 4];
            *(float4*)&b[0] = *(const float4*)&Ws[kk][tx * 8];
            *(float4*)&b[4] = *(const float4*)&Ws[kk][tx * 8 + 4];
            #pragma unroll
            for (int i = 0; i < 8; i++)
                #pragma unroll
                for (int j = 0; j < 8; j++)
                    acc[i][j] += a[i] * b[j];
        }
    }

    // Epilogue
    #pragma unroll
    for (int i = 0; i < 8; i++) {
        const int row = br * 128 + ty * 8 + i;
        #pragma unroll
        for (int j4 = 0; j4 < 8; j4 += 4) {
            const int col = bc * 128 + tx * 8 + j4;
            float4 v;
            v.x = acc[i][j4 + 0]; v.y = acc[i][j4 + 1];
            v.z = acc[i][j4 + 2]; v.w = acc[i][j4 + 3];
            if (SCATTER_C) {
                const int b = row >> 11, s = row & 2047;
                const int h = col >> 6,  d = col & 63;
                *(float4*)&C[((((b << 4) + h) * S_LEN + s) * HDIM) + d] = v;
            } else {
                *(float4*)&C[row * DMODEL + col] = v;
            }
        }
    }
}

// ---------------------------------------------------------------------------
// Causal flash attention, fp32. One thread per query row; 128 q-rows/block.
// K/V streamed through SMEM in 32-key tiles, broadcast LDS.128 reads.
// grid = (S/128, B*H), block = 128
// ---------------------------------------------------------------------------
__global__ void __launch_bounds__(128)
attn_kernel(const float* __restrict__ Q, const float* __restrict__ K,
            const float* __restrict__ V, float* __restrict__ O)
{
    __shared__ float Ks[32][64];
    __shared__ float Vs[32][64];

    const int tid = threadIdx.x;
    const int q0  = blockIdx.x * 128;
    const int bh  = blockIdx.y;
    const long base = (long)bh * S_LEN * HDIM;
    const int  r  = q0 + tid;           // this thread's query row

    // q row in registers (16 x float4)
    float4 qv[16];
    const float4* qp = (const float4*)&Q[base + (long)r * HDIM];
    #pragma unroll
    for (int d = 0; d < 16; d++) qv[d] = qp[d];

    float4 av[16];
    #pragma unroll
    for (int d = 0; d < 16; d++) { av[d].x = av[d].y = av[d].z = av[d].w = 0.0f; }

    float m_i = -1e30f, l_i = 0.0f;
    const float scale = 0.125f;   // 1/sqrt(64)

    const int ntiles = (q0 + 128) / 32;   // causal: keys up to q0+127
    for (int kt = 0; kt < ntiles; kt++) {
        __syncthreads();
        #pragma unroll
        for (int i = 0; i < 4; i++) {
            const int f = i * 128 + tid;          // float4 slot 0..511
            const int rr = f >> 4, c4 = (f & 15) * 4;
            const long g = base + (long)(kt * 32 + rr) * HDIM + c4;
            *(float4*)&Ks[rr][c4] = *(const float4*)&K[g];
            *(float4*)&Vs[rr][c4] = *(const float4*)&V[g];
        }
        __syncthreads();

        // scores for 32 keys
        float sc[32];
        float smax = m_i;
        #pragma unroll
        for (int j = 0; j < 32; j++) {
            const float4* kp = (const float4*)&Ks[j][0];
            float4 s4; s4.x = s4.y = s4.z = s4.w = 0.0f;
            #pragma unroll
            for (int d = 0; d < 16; d++) {
                const float4 kv = kp[d];
                s4.x += qv[d].x * kv.x; s4.y += qv[d].y * kv.y;
                s4.z += qv[d].z * kv.z; s4.w += qv[d].w * kv.w;
            }
            float s = ((s4.x + s4.y) + (s4.z + s4.w)) * scale;
            if (kt * 32 + j > r) s = -1e30f;      // causal mask
            sc[j] = s;
            smax = fmaxf(smax, s);
        }

        // rescale running state
        const float corr = __expf(m_i - smax);
        l_i *= corr;
        #pragma unroll
        for (int d = 0; d < 16; d++) {
            av[d].x *= corr; av[d].y *= corr; av[d].z *= corr; av[d].w *= corr;
        }

        // accumulate P @ V
        #pragma unroll
        for (int j = 0; j < 32; j++) {
            const float p = __expf(sc[j] - smax);
            l_i += p;
            const float4* vp = (const float4*)&Vs[j][0];
            #pragma unroll
            for (int d = 0; d < 16; d++) {
                const float4 vv = vp[d];
                av[d].x += p * vv.x; av[d].y += p * vv.y;
                av[d].z += p * vv.z; av[d].w += p * vv.w;
            }
        }
        m_i = smax;
    }

    const float inv = 1.0f / l_i;
    float4* op = (float4*)&O[base + (long)r * HDIM];
    #pragma unroll
    for (int d = 0; d < 16; d++) {
        float4 v = av[d];
        v.x *= inv; v.y *= inv; v.z *= inv; v.w *= inv;
        op[d] = v;
    }
}

// ---------------------------------------------------------------------------
extern "C" void kernel_launch(void* const* d_in, const int* in_sizes, int n_in,
                              void* d_out, int out_size)
{
    const float* q  = (const float*)d_in[0];
    const float* k  = (const float*)d_in[1];
    const float* v  = (const float*)d_in[2];
    const float* wq = (const float*)d_in[3];
    const float* wk = (const float*)d_in[4];
    const float* wv = (const float*)d_in[5];
    const float* wo = (const float*)d_in[6];
    float* out = (float*)d_out;

    float *pQ, *pK, *pV, *pO;
    cudaGetSymbolAddress((void**)&pQ, g_Q);
    cudaGetSymbolAddress((void**)&pK, g_K);
    cudaGetSymbolAddress((void**)&pV, g_V);
    cudaGetSymbolAddress((void**)&pO, g_O);

    dim3 gg(DMODEL / 128, MROWS / 128);   // (8, 64)

    gemm_kernel<false, true><<<gg, 256>>>(q, wq, pQ);
    gemm_kernel<false, true><<<gg, 256>>>(k, wk, pK);
    gemm_kernel<false, true><<<gg, 256>>>(v, wv, pV);

    attn_kernel<<<dim3(S_LEN / 128, BHCNT), 128>>>(pQ, pK, pV, pO);

    gemm_kernel<true, false><<<gg, 256>>>(pO, wo, out);
}

// round 3
// speedup vs baseline: 1.3424x; 1.3424x over previous
#include <cuda_runtime.h>
#include <cuda_bf16.h>
#include <cstdint>

#define S_LEN   2048
#define DMODEL  1024
#define NHEADS  16
#define HDIM    64
#define BATCH   4
#define BHCNT   (BATCH * NHEADS)                   // 64
#define MROWS   (BATCH * S_LEN)                    // 8192
#define HS_ELEMS (BATCH * NHEADS * S_LEN * HDIM)   // 8388608
#define AELEMS  (MROWS * DMODEL)                   // 8388608
#define WELEMS  (DMODEL * DMODEL)                  // 1048576

// ---- scratch ----
__device__ float g_Q[HS_ELEMS];
__device__ float g_K[HS_ELEMS];
__device__ float g_V[HS_ELEMS];
__device__ float g_O[HS_ELEMS];
__device__ __nv_bfloat16 g_Ahi[AELEMS];
__device__ __nv_bfloat16 g_Alo[AELEMS];
__device__ __nv_bfloat16 g_Whi[4][WELEMS];   // transposed [N][K]
__device__ __nv_bfloat16 g_Wlo[4][WELEMS];

// ============================================================================
// helpers (baseline PTX only: mma.sync / ldmatrix / cp.async)
// ============================================================================
__device__ __forceinline__ uint32_t smem_u32(const void* p) {
    uint32_t a;
    asm("{ .reg .u64 t; cvta.to.shared.u64 t, %1; cvt.u32.u64 %0, t; }"
        : "=r"(a) : "l"(p));
    return a;
}
__device__ __forceinline__ void cp_async16(uint32_t dst, const void* src) {
    asm volatile("cp.async.cg.shared.global [%0], [%1], 16;"
                 :: "r"(dst), "l"(src));
}
__device__ __forceinline__ void cp_commit() {
    asm volatile("cp.async.commit_group;");
}
template <int N>
__device__ __forceinline__ void cp_wait() {
    asm volatile("cp.async.wait_group %0;" :: "n"(N));
}
__device__ __forceinline__ void ldsm_x4(uint32_t* r, uint32_t addr) {
    asm volatile("ldmatrix.sync.aligned.m8n8.x4.shared.b16 {%0,%1,%2,%3}, [%4];"
                 : "=r"(r[0]), "=r"(r[1]), "=r"(r[2]), "=r"(r[3]) : "r"(addr));
}
__device__ __forceinline__ void mma16816(float* d, const uint32_t* a,
                                         const uint32_t* b) {
    asm volatile("mma.sync.aligned.m16n8k16.row.col.f32.bf16.bf16.f32 "
                 "{%0,%1,%2,%3}, {%4,%5,%6,%7}, {%8,%9}, {%0,%1,%2,%3};"
                 : "+f"(d[0]), "+f"(d[1]), "+f"(d[2]), "+f"(d[3])
                 : "r"(a[0]), "r"(a[1]), "r"(a[2]), "r"(a[3]),
                   "r"(b[0]), "r"(b[1]));
}

// SMEM geometry: rows of 32 bf16 padded to 80B (conflict-free ldmatrix phases)
#define ROWB       80
#define MAT_BYTES  (128 * ROWB)        // 10240
#define STG_BYTES  (4 * MAT_BYTES)     // 40960 (Ahi, Alo, Bhi, Blo)
#define SMEM_TOTAL (2 * STG_BYTES)     // 81920

// ============================================================================
// Split-bf16 3-term GEMM on mma.sync:
//   C[8192,1024] = Ahi@Bt^T + Ahi@BtLo^T + Alo@Bt^T   (Bt stored [N][K])
// block 128x128, BK=32, 256 thr (8 warps: 4(M) x 2(N)), warp tile 32x64.
// 2-stage cp.async pipeline. SCATTER_C writes head-split [b,h,s,d].
// ============================================================================
template <bool SCATTER_C>
__global__ void __launch_bounds__(256, 1)
gemm_mma3(const __nv_bfloat16* __restrict__ Ahi,
          const __nv_bfloat16* __restrict__ Alo,
          const __nv_bfloat16* __restrict__ Bhi,
          const __nv_bfloat16* __restrict__ Blo,
          float* __restrict__ C)
{
    extern __shared__ char smem[];
    const uint32_t sb = smem_u32(smem);
    const int tid  = threadIdx.x;
    const int wid  = tid >> 5;
    const int lane = tid & 31;
    const int warp_m = wid >> 1;      // 0..3
    const int warp_n = wid & 1;       // 0..1
    const int bc = blockIdx.x;        // N tile
    const int br = blockIdx.y;        // M tile

    float acc[2][8][4];
    #pragma unroll
    for (int mt = 0; mt < 2; mt++)
        #pragma unroll
        for (int nt = 0; nt < 8; nt++)
            #pragma unroll
            for (int i = 0; i < 4; i++) acc[mt][nt][i] = 0.0f;

    // per-thread load slots: 2048 16B-chunks per stage, 8 per thread
    // chunk c: mat = c>>9 (0:Ahi 1:Alo 2:Bhi 3:Blo), row = (c&511)>>2, seg = c&3
    auto issue = [&](int kc, int stage) {
        #pragma unroll
        for (int t = 0; t < 8; t++) {
            const int c   = tid + t * 256;
            const int mat = c >> 9;
            const int rem = c & 511;
            const int row = rem >> 2;
            const int seg = rem & 3;
            const long gcol = (long)kc * 32 + seg * 8;
            const __nv_bfloat16* g;
            if (mat == 0)      g = Ahi + (long)(br * 128 + row) * DMODEL + gcol;
            else if (mat == 1) g = Alo + (long)(br * 128 + row) * DMODEL + gcol;
            else if (mat == 2) g = Bhi + (long)(bc * 128 + row) * DMODEL + gcol;
            else               g = Blo + (long)(bc * 128 + row) * DMODEL + gcol;
            const uint32_t dst = sb + stage * STG_BYTES + mat * MAT_BYTES
                               + row * ROWB + seg * 16;
            cp_async16(dst, g);
        }
        cp_commit();
    };

    issue(0, 0);

    for (int kc = 0; kc < DMODEL / 32; kc++) {
        const int stage = kc & 1;
        __syncthreads();                       // buf (kc+1)&1 free to overwrite
        if (kc + 1 < DMODEL / 32) issue(kc + 1, stage ^ 1);
        if (kc + 1 < DMODEL / 32) cp_wait<1>(); else cp_wait<0>();
        __syncthreads();                       // stage data visible to all

        const uint32_t base = sb + stage * STG_BYTES;

        #pragma unroll
        for (int kk = 0; kk < 2; kk++) {
            // ---- A fragments (hi, lo) for both m16 tiles ----
            uint32_t ahi[2][4], alo[2][4];
            {
                const uint32_t arow = warp_m * 32 + (lane & 15);
                const uint32_t acol = kk * 16 + (lane >> 4) * 8;
                const uint32_t off  = arow * ROWB + acol * 2;
                ldsm_x4(ahi[0], base + off);
                ldsm_x4(ahi[1], base + off + 16 * ROWB);
                ldsm_x4(alo[0], base + MAT_BYTES + off);
                ldsm_x4(alo[1], base + MAT_BYTES + off + 16 * ROWB);
            }
            // ---- B fragments: 4 x4-loads each cover two n8 tiles ----
            uint32_t bhi[4][4], blo[4][4];
            {
                const uint32_t brow = warp_n * 64 + (lane & 7) + ((lane & 16) >> 1);
                const uint32_t bcol = kk * 16 + ((lane >> 3) & 1) * 8;
                const uint32_t off  = brow * ROWB + bcol * 2;
                #pragma unroll
                for (int q = 0; q < 4; q++) {
                    ldsm_x4(bhi[q], base + 2 * MAT_BYTES + off + q * 16 * ROWB);
                    ldsm_x4(blo[q], base + 3 * MAT_BYTES + off + q * 16 * ROWB);
                }
            }
            // ---- 48 MMAs: 3 terms x 2 m-tiles x 8 n-tiles ----
            #pragma unroll
            for (int mt = 0; mt < 2; mt++)
                #pragma unroll
                for (int nt = 0; nt < 8; nt++) {
                    const uint32_t* bh = &bhi[nt >> 1][(nt & 1) * 2];
                    const uint32_t* bl = &blo[nt >> 1][(nt & 1) * 2];
                    mma16816(acc[mt][nt], ahi[mt], bh);
                    mma16816(acc[mt][nt], ahi[mt], bl);
                    mma16816(acc[mt][nt], alo[mt], bh);
                }
        }
    }

    // ---- epilogue ----
    #pragma unroll
    for (int mt = 0; mt < 2; mt++) {
        #pragma unroll
        for (int nt = 0; nt < 8; nt++) {
            const int row0 = br * 128 + warp_m * 32 + mt * 16 + (lane >> 2);
            const int col  = bc * 128 + warp_n * 64 + nt * 8 + (lane & 3) * 2;
            float2 v01; v01.x = acc[mt][nt][0]; v01.y = acc[mt][nt][1];
            float2 v23; v23.x = acc[mt][nt][2]; v23.y = acc[mt][nt][3];
            if (SCATTER_C) {
                const int h = col >> 6, dd = col & 63;
                const int b0 = row0 >> 11, s0 = row0 & 2047;
                *(float2*)&C[((((long)b0 * NHEADS + h) * S_LEN + s0) * HDIM) + dd] = v01;
                const int r2 = row0 + 8;
                const int b2 = r2 >> 11, s2 = r2 & 2047;
                *(float2*)&C[((((long)b2 * NHEADS + h) * S_LEN + s2) * HDIM) + dd] = v23;
            } else {
                *(float2*)&C[(long)row0 * DMODEL + col] = v01;
                *(float2*)&C[(long)(row0 + 8) * DMODEL + col] = v23;
            }
        }
    }
}

// ============================================================================
// fp32 -> (hi, lo) bf16 split, elementwise (row-major A matrices)
// ============================================================================
__global__ void __launch_bounds__(256)
conv_split(const float* __restrict__ X, __nv_bfloat16* __restrict__ hi,
           __nv_bfloat16* __restrict__ lo)
{
    const int i = blockIdx.x * 256 + threadIdx.x;   // over float2
    const float2 x = ((const float2*)X)[i];
    const __nv_bfloat16 h0 = __float2bfloat16(x.x);
    const __nv_bfloat16 h1 = __float2bfloat16(x.y);
    const __nv_bfloat16 l0 = __float2bfloat16(x.x - __bfloat162float(h0));
    const __nv_bfloat16 l1 = __float2bfloat16(x.y - __bfloat162float(h1));
    ((__nv_bfloat162*)hi)[i] = __halves2bfloat162(h0, h1);
    ((__nv_bfloat162*)lo)[i] = __halves2bfloat162(l0, l1);
}

// W fp32 [K][N] -> transposed split bf16 [N][K]
__global__ void __launch_bounds__(256)
conv_w(const float* __restrict__ W, __nv_bfloat16* __restrict__ hi,
       __nv_bfloat16* __restrict__ lo)
{
    __shared__ float t[32][33];
    const int tx = threadIdx.x, ty = threadIdx.y;     // (32, 8)
    const int n0 = blockIdx.x * 32, k0 = blockIdx.y * 32;
    #pragma unroll
    for (int r = 0; r < 4; r++) {
        const int k = ty + r * 8;
        t[k][tx] = W[(long)(k0 + k) * DMODEL + n0 + tx];
    }
    __syncthreads();
    #pragma unroll
    for (int r = 0; r < 4; r++) {
        const int nl = ty + r * 8;
        const float x = t[tx][nl];
        const __nv_bfloat16 h = __float2bfloat16(x);
        const long o = (long)(n0 + nl) * DMODEL + k0 + tx;
        hi[o] = h;
        lo[o] = __float2bfloat16(x - __bfloat162float(h));
    }
}

// head-split fp32 O [b,h,s,d] -> row-major split bf16 [b*S+s][h*64+d]
__global__ void __launch_bounds__(256)
conv_o(const float* __restrict__ O, __nv_bfloat16* __restrict__ hi,
       __nv_bfloat16* __restrict__ lo)
{
    const int i = blockIdx.x * 256 + threadIdx.x;     // over float2
    const int row = i >> 9;                           // 512 float2 per row
    const int col = (i & 511) * 2;
    const int b = row >> 11, s = row & 2047;
    const int h = col >> 6, d = col & 63;
    const float2 x = *(const float2*)&O[((((long)b * NHEADS + h) * S_LEN + s) * HDIM) + d];
    const __nv_bfloat16 h0 = __float2bfloat16(x.x);
    const __nv_bfloat16 h1 = __float2bfloat16(x.y);
    const __nv_bfloat16 l0 = __float2bfloat16(x.x - __bfloat162float(h0));
    const __nv_bfloat16 l1 = __float2bfloat16(x.y - __bfloat162float(h1));
    ((__nv_bfloat162*)hi)[i] = __halves2bfloat162(h0, h1);
    ((__nv_bfloat162*)lo)[i] = __halves2bfloat162(l0, l1);
}

// ============================================================================
// Causal flash attention, fp32 (unchanged from R1)
// ============================================================================
__global__ void __launch_bounds__(128)
attn_kernel(const float* __restrict__ Q, const float* __restrict__ K,
            const float* __restrict__ V, float* __restrict__ O)
{
    __shared__ float Ks[32][64];
    __shared__ float Vs[32][64];

    const int tid = threadIdx.x;
    const int q0  = blockIdx.x * 128;
    const int bh  = blockIdx.y;
    const long base = (long)bh * S_LEN * HDIM;
    const int  r  = q0 + tid;

    float4 qv[16];
    const float4* qp = (const float4*)&Q[base + (long)r * HDIM];
    #pragma unroll
    for (int d = 0; d < 16; d++) qv[d] = qp[d];

    float4 av[16];
    #pragma unroll
    for (int d = 0; d < 16; d++) { av[d].x = av[d].y = av[d].z = av[d].w = 0.0f; }

    float m_i = -1e30f, l_i = 0.0f;
    const float scale = 0.125f;

    const int ntiles = (q0 + 128) / 32;
    for (int kt = 0; kt < ntiles; kt++) {
        __syncthreads();
        #pragma unroll
        for (int i = 0; i < 4; i++) {
            const int f = i * 128 + tid;
            const int rr = f >> 4, c4 = (f & 15) * 4;
            const long g = base + (long)(kt * 32 + rr) * HDIM + c4;
            *(float4*)&Ks[rr][c4] = *(const float4*)&K[g];
            *(float4*)&Vs[rr][c4] = *(const float4*)&V[g];
        }
        __syncthreads();

        float sc[32];
        float smax = m_i;
        #pragma unroll
        for (int j = 0; j < 32; j++) {
            const float4* kp = (const float4*)&Ks[j][0];
            float4 s4; s4.x = s4.y = s4.z = s4.w = 0.0f;
            #pragma unroll
            for (int d = 0; d < 16; d++) {
                const float4 kv = kp[d];
                s4.x += qv[d].x * kv.x; s4.y += qv[d].y * kv.y;
                s4.z += qv[d].z * kv.z; s4.w += qv[d].w * kv.w;
            }
            float s = ((s4.x + s4.y) + (s4.z + s4.w)) * scale;
            if (kt * 32 + j > r) s = -1e30f;
            sc[j] = s;
            smax = fmaxf(smax, s);
        }

        const float corr = __expf(m_i - smax);
        l_i *= corr;
        #pragma unroll
        for (int d = 0; d < 16; d++) {
            av[d].x *= corr; av[d].y *= corr; av[d].z *= corr; av[d].w *= corr;
        }

        #pragma unroll
        for (int j = 0; j < 32; j++) {
            const float p = __expf(sc[j] - smax);
            l_i += p;
            const float4* vp = (const float4*)&Vs[j][0];
            #pragma unroll
            for (int d = 0; d < 16; d++) {
                const float4 vv = vp[d];
                av[d].x += p * vv.x; av[d].y += p * vv.y;
                av[d].z += p * vv.z; av[d].w += p * vv.w;
            }
        }
        m_i = smax;
    }

    const float inv = 1.0f / l_i;
    float4* op = (float4*)&O[base + (long)r * HDIM];
    #pragma unroll
    for (int d = 0; d < 16; d++) {
        float4 v = av[d];
        v.x *= inv; v.y *= inv; v.z *= inv; v.w *= inv;
        op[d] = v;
    }
}

// ============================================================================
extern "C" void kernel_launch(void* const* d_in, const int* in_sizes, int n_in,
                              void* d_out, int out_size)
{
    const float* q  = (const float*)d_in[0];
    const float* k  = (const float*)d_in[1];
    const float* v  = (const float*)d_in[2];
    const float* w[4] = { (const float*)d_in[3], (const float*)d_in[4],
                          (const float*)d_in[5], (const float*)d_in[6] };
    float* out = (float*)d_out;

    float *pQ, *pK, *pV, *pO;
    cudaGetSymbolAddress((void**)&pQ, g_Q);
    cudaGetSymbolAddress((void**)&pK, g_K);
    cudaGetSymbolAddress((void**)&pV, g_V);
    cudaGetSymbolAddress((void**)&pO, g_O);
    __nv_bfloat16 *ahi, *alo, *whi, *wlo;
    cudaGetSymbolAddress((void**)&ahi, g_Ahi);
    cudaGetSymbolAddress((void**)&alo, g_Alo);
    cudaGetSymbolAddress((void**)&whi, g_Whi);
    cudaGetSymbolAddress((void**)&wlo, g_Wlo);

    cudaFuncSetAttribute((const void*)gemm_mma3<true>,
                         cudaFuncAttributeMaxDynamicSharedMemorySize, SMEM_TOTAL);
    cudaFuncSetAttribute((const void*)gemm_mma3<false>,
                         cudaFuncAttributeMaxDynamicSharedMemorySize, SMEM_TOTAL);

    const dim3 wgrid(32, 32), wblk(32, 8);
    for (int i = 0; i < 4; i++)
        conv_w<<<wgrid, wblk>>>(w[i], whi + (long)i * WELEMS, wlo + (long)i * WELEMS);

    const dim3 gg(8, 64);
    const int nConvBlocks = AELEMS / 2 / 256;   // 16384

    conv_split<<<nConvBlocks, 256>>>(q, ahi, alo);
    gemm_mma3<true><<<gg, 256, SMEM_TOTAL>>>(ahi, alo, whi + 0 * (long)WELEMS,
                                             wlo + 0 * (long)WELEMS, pQ);
    conv_split<<<nConvBlocks, 256>>>(k, ahi, alo);
    gemm_mma3<true><<<gg, 256, SMEM_TOTAL>>>(ahi, alo, whi + 1 * (long)WELEMS,
                                             wlo + 1 * (long)WELEMS, pK);
    conv_split<<<nConvBlocks, 256>>>(v, ahi, alo);
    gemm_mma3<true><<<gg, 256, SMEM_TOTAL>>>(ahi, alo, whi + 2 * (long)WELEMS,
                                             wlo + 2 * (long)WELEMS, pV);

    attn_kernel<<<dim3(S_LEN / 128, BHCNT), 128>>>(pQ, pK, pV, pO);

    conv_o<<<nConvBlocks, 256>>>(pO, ahi, alo);
    gemm_mma3<false><<<gg, 256, SMEM_TOTAL>>>(ahi, alo, whi + 3 * (long)WELEMS,
                                              wlo + 3 * (long)WELEMS, out);
}

// round 4
// speedup vs baseline: 3.1303x; 2.3320x over previous
#include <cuda_runtime.h>
#include <cuda_bf16.h>
#include <cstdint>

#define S_LEN   2048
#define DMODEL  1024
#define NHEADS  16
#define HDIM    64
#define BATCH   4
#define BHCNT   (BATCH * NHEADS)                   // 64
#define MROWS   (BATCH * S_LEN)                    // 8192
#define HS_ELEMS (BATCH * NHEADS * S_LEN * HDIM)   // 8388608
#define AELEMS  (MROWS * DMODEL)                   // 8388608
#define WELEMS  (DMODEL * DMODEL)                  // 1048576

// ---- scratch (all bf16 hi/lo pairs) ----
__device__ __nv_bfloat16 g_Ahi[AELEMS];
__device__ __nv_bfloat16 g_Alo[AELEMS];
__device__ __nv_bfloat16 g_Whi[4][WELEMS];   // transposed [N][K]
__device__ __nv_bfloat16 g_Wlo[4][WELEMS];
__device__ __nv_bfloat16 g_Qhi[HS_ELEMS], g_Qlo[HS_ELEMS];   // head-split, pre-scaled 1/8
__device__ __nv_bfloat16 g_Khi[HS_ELEMS], g_Klo[HS_ELEMS];
__device__ __nv_bfloat16 g_Vhi[HS_ELEMS], g_Vlo[HS_ELEMS];
__device__ __nv_bfloat16 g_Ohi[AELEMS],  g_Olo[AELEMS];      // row-major [8192][1024]

// ============================================================================
// helpers (baseline PTX only)
// ============================================================================
__device__ __forceinline__ uint32_t smem_u32(const void* p) {
    uint32_t a;
    asm("{ .reg .u64 t; cvta.to.shared.u64 t, %1; cvt.u32.u64 %0, t; }"
        : "=r"(a) : "l"(p));
    return a;
}
__device__ __forceinline__ void cp_async16(uint32_t dst, const void* src) {
    asm volatile("cp.async.cg.shared.global [%0], [%1], 16;"
                 :: "r"(dst), "l"(src));
}
__device__ __forceinline__ void cp_commit() {
    asm volatile("cp.async.commit_group;");
}
template <int N>
__device__ __forceinline__ void cp_wait() {
    asm volatile("cp.async.wait_group %0;" :: "n"(N));
}
__device__ __forceinline__ void ldsm_x4(uint32_t* r, uint32_t addr) {
    asm volatile("ldmatrix.sync.aligned.m8n8.x4.shared.b16 {%0,%1,%2,%3}, [%4];"
                 : "=r"(r[0]), "=r"(r[1]), "=r"(r[2]), "=r"(r[3]) : "r"(addr));
}
__device__ __forceinline__ void ldsm_x4t(uint32_t* r, uint32_t addr) {
    asm volatile("ldmatrix.sync.aligned.m8n8.x4.trans.shared.b16 {%0,%1,%2,%3}, [%4];"
                 : "=r"(r[0]), "=r"(r[1]), "=r"(r[2]), "=r"(r[3]) : "r"(addr));
}
__device__ __forceinline__ void mma16816(float* d, const uint32_t* a,
                                         const uint32_t* b) {
    asm volatile("mma.sync.aligned.m16n8k16.row.col.f32.bf16.bf16.f32 "
                 "{%0,%1,%2,%3}, {%4,%5,%6,%7}, {%8,%9}, {%0,%1,%2,%3};"
                 : "+f"(d[0]), "+f"(d[1]), "+f"(d[2]), "+f"(d[3])
                 : "r"(a[0]), "r"(a[1]), "r"(a[2]), "r"(a[3]),
                   "r"(b[0]), "r"(b[1]));
}
__device__ __forceinline__ void split2(float a, float b,
                                       uint32_t& hi, uint32_t& lo) {
    __nv_bfloat16 ha = __float2bfloat16(a), hb = __float2bfloat16(b);
    __nv_bfloat16 la = __float2bfloat16(a - __bfloat162float(ha));
    __nv_bfloat16 lb = __float2bfloat16(b - __bfloat162float(hb));
    hi = (uint32_t)*(uint16_t*)&ha | ((uint32_t)*(uint16_t*)&hb << 16);
    lo = (uint32_t)*(uint16_t*)&la | ((uint32_t)*(uint16_t*)&lb << 16);
}

// ============================================================================
// Split-bf16 3-term GEMM (mma.sync), 128x128 tile, BK=32, 8 warps.
// SPLIT=true : C -> bf16 hi/lo pairs, head-split [bh][s][d], scaled.
// SPLIT=false: C -> fp32 row-major.
// ============================================================================
#define ROWB       80
#define MAT_BYTES  (128 * ROWB)
#define STG_BYTES  (4 * MAT_BYTES)
#define GSMEM      (2 * STG_BYTES)      // 81920

template <bool SPLIT>
__global__ void __launch_bounds__(256, 1)
gemm_mma3(const __nv_bfloat16* __restrict__ Ahi,
          const __nv_bfloat16* __restrict__ Alo,
          const __nv_bfloat16* __restrict__ Bhi,
          const __nv_bfloat16* __restrict__ Blo,
          float* __restrict__ Cf,
          __nv_bfloat16* __restrict__ Chi,
          __nv_bfloat16* __restrict__ Clo,
          float scale)
{
    extern __shared__ char smem[];
    const uint32_t sb = smem_u32(smem);
    const int tid  = threadIdx.x;
    const int wid  = tid >> 5;
    const int lane = tid & 31;
    const int warp_m = wid >> 1;
    const int warp_n = wid & 1;
    const int bc = blockIdx.x;
    const int br = blockIdx.y;

    float acc[2][8][4];
    #pragma unroll
    for (int mt = 0; mt < 2; mt++)
        #pragma unroll
        for (int nt = 0; nt < 8; nt++)
            #pragma unroll
            for (int i = 0; i < 4; i++) acc[mt][nt][i] = 0.0f;

    auto issue = [&](int kc, int stage) {
        #pragma unroll
        for (int t = 0; t < 8; t++) {
            const int c   = tid + t * 256;
            const int mat = c >> 9;
            const int rem = c & 511;
            const int row = rem >> 2;
            const int seg = rem & 3;
            const long gcol = (long)kc * 32 + seg * 8;
            const __nv_bfloat16* g;
            if (mat == 0)      g = Ahi + (long)(br * 128 + row) * DMODEL + gcol;
            else if (mat == 1) g = Alo + (long)(br * 128 + row) * DMODEL + gcol;
            else if (mat == 2) g = Bhi + (long)(bc * 128 + row) * DMODEL + gcol;
            else               g = Blo + (long)(bc * 128 + row) * DMODEL + gcol;
            cp_async16(sb + stage * STG_BYTES + mat * MAT_BYTES
                       + row * ROWB + seg * 16, g);
        }
        cp_commit();
    };

    issue(0, 0);

    for (int kc = 0; kc < DMODEL / 32; kc++) {
        const int stage = kc & 1;
        __syncthreads();
        if (kc + 1 < DMODEL / 32) { issue(kc + 1, stage ^ 1); cp_wait<1>(); }
        else                      { cp_wait<0>(); }
        __syncthreads();

        const uint32_t base = sb + stage * STG_BYTES;

        #pragma unroll
        for (int kk = 0; kk < 2; kk++) {
            uint32_t ahi[2][4], alo[2][4];
            {
                const uint32_t arow = warp_m * 32 + (lane & 15);
                const uint32_t acol = kk * 16 + (lane >> 4) * 8;
                const uint32_t off  = arow * ROWB + acol * 2;
                ldsm_x4(ahi[0], base + off);
                ldsm_x4(ahi[1], base + off + 16 * ROWB);
                ldsm_x4(alo[0], base + MAT_BYTES + off);
                ldsm_x4(alo[1], base + MAT_BYTES + off + 16 * ROWB);
            }
            uint32_t bhi[4][4], blo[4][4];
            {
                const uint32_t brow = warp_n * 64 + (lane & 7) + ((lane & 16) >> 1);
                const uint32_t bcol = kk * 16 + ((lane >> 3) & 1) * 8;
                const uint32_t off  = brow * ROWB + bcol * 2;
                #pragma unroll
                for (int q = 0; q < 4; q++) {
                    ldsm_x4(bhi[q], base + 2 * MAT_BYTES + off + q * 16 * ROWB);
                    ldsm_x4(blo[q], base + 3 * MAT_BYTES + off + q * 16 * ROWB);
                }
            }
            #pragma unroll
            for (int mt = 0; mt < 2; mt++)
                #pragma unroll
                for (int nt = 0; nt < 8; nt++) {
                    const uint32_t* bh = &bhi[nt >> 1][(nt & 1) * 2];
                    const uint32_t* bl = &blo[nt >> 1][(nt & 1) * 2];
                    mma16816(acc[mt][nt], ahi[mt], bh);
                    mma16816(acc[mt][nt], ahi[mt], bl);
                    mma16816(acc[mt][nt], alo[mt], bh);
                }
        }
    }

    #pragma unroll
    for (int mt = 0; mt < 2; mt++) {
        #pragma unroll
        for (int nt = 0; nt < 8; nt++) {
            const int row0 = br * 128 + warp_m * 32 + mt * 16 + (lane >> 2);
            const int col  = bc * 128 + warp_n * 64 + nt * 8 + (lane & 3) * 2;
            if (SPLIT) {
                const int h = col >> 6, dd = col & 63;
                #pragma unroll
                for (int half = 0; half < 2; half++) {
                    const int r = row0 + half * 8;
                    const int b = r >> 11, s = r & 2047;
                    const long off = ((((long)b * NHEADS + h) * S_LEN + s) * HDIM) + dd;
                    uint32_t hi, lo;
                    split2(acc[mt][nt][half * 2] * scale,
                           acc[mt][nt][half * 2 + 1] * scale, hi, lo);
                    *(uint32_t*)(Chi + off) = hi;
                    *(uint32_t*)(Clo + off) = lo;
                }
            } else {
                float2 v01; v01.x = acc[mt][nt][0]; v01.y = acc[mt][nt][1];
                float2 v23; v23.x = acc[mt][nt][2]; v23.y = acc[mt][nt][3];
                *(float2*)&Cf[(long)row0 * DMODEL + col] = v01;
                *(float2*)&Cf[(long)(row0 + 8) * DMODEL + col] = v23;
            }
        }
    }
}

// ============================================================================
// Tensor-core causal flash attention (split-bf16 3-term).
// grid (16, 64), block 256 (8 warps x m16). K-tiles of 64, double-buffered.
// Q pre-scaled by 1/8. Output -> bf16 hi/lo, row-major [8192][1024].
// ============================================================================
#define AROWB   144                     // 64 bf16 = 128B + 16B pad
#define QH_OFF  0
#define QL_OFF  (128 * AROWB)           // 18432
#define KV_OFF  (2 * 128 * AROWB)       // 36864
#define KV_STG  (4 * 64 * AROWB)        // 36864 per stage
#define ASMEM   (KV_OFF + 2 * KV_STG)   // 110592

__global__ void __launch_bounds__(256, 1)
attn_mma(const __nv_bfloat16* __restrict__ Qhi, const __nv_bfloat16* __restrict__ Qlo,
         const __nv_bfloat16* __restrict__ Khi, const __nv_bfloat16* __restrict__ Klo,
         const __nv_bfloat16* __restrict__ Vhi, const __nv_bfloat16* __restrict__ Vlo,
         __nv_bfloat16* __restrict__ Ohi, __nv_bfloat16* __restrict__ Olo)
{
    extern __shared__ char smem[];
    const uint32_t sb = smem_u32(smem);
    const int tid = threadIdx.x, wid = tid >> 5, lane = tid & 31;
    const int q0 = blockIdx.x * 128;
    const int bh = blockIdx.y;
    const long base = (long)bh * S_LEN * HDIM;

    // ---- load Q hi/lo ----
    {
        #pragma unroll
        for (int t = 0; t < 8; t++) {
            const int c = tid + t * 256;            // 0..2047
            const int arr = c >> 10, rem = c & 1023;
            const int row = rem >> 3, seg = rem & 7;
            const __nv_bfloat16* src = (arr ? Qlo : Qhi)
                                     + base + (long)(q0 + row) * HDIM + seg * 8;
            cp_async16(sb + (arr ? QL_OFF : QH_OFF) + row * AROWB + seg * 16, src);
        }
        cp_commit();
    }

    const int ntiles = blockIdx.x * 2 + 2;

    auto kv_issue = [&](int t, int stage) {
        #pragma unroll
        for (int i = 0; i < 8; i++) {
            const int c = tid + i * 256;            // 0..2047
            const int arr = c >> 9, rem = c & 511;
            const int row = rem >> 3, seg = rem & 7;
            const __nv_bfloat16* p;
            if (arr == 0)      p = Khi;
            else if (arr == 1) p = Klo;
            else if (arr == 2) p = Vhi;
            else               p = Vlo;
            cp_async16(sb + KV_OFF + stage * KV_STG + arr * (64 * AROWB)
                       + row * AROWB + seg * 16,
                       p + base + (long)(t * 64 + row) * HDIM + seg * 8);
        }
        cp_commit();
    };

    kv_issue(0, 0);
    cp_wait<1>();          // Q resident
    __syncthreads();

    // ---- persistent Q fragments ----
    uint32_t qhF[4][4], qlF[4][4];
    {
        const uint32_t arow = wid * 16 + (lane & 15);
        #pragma unroll
        for (int kt = 0; kt < 4; kt++) {
            const uint32_t off = arow * AROWB + (kt * 16 + (lane >> 4) * 8) * 2;
            ldsm_x4(qhF[kt], sb + QH_OFF + off);
            ldsm_x4(qlF[kt], sb + QL_OFF + off);
        }
    }

    float m_s[2] = {-1e30f, -1e30f};
    float l_s[2] = {0.0f, 0.0f};
    float acc_o[8][4];
    #pragma unroll
    for (int nt = 0; nt < 8; nt++)
        #pragma unroll
        for (int i = 0; i < 4; i++) acc_o[nt][i] = 0.0f;

    const int wrow_lo = q0 + wid * 16;       // warp's min q-row

    for (int t = 0; t < ntiles; t++) {
        const int stage = t & 1;
        __syncthreads();                                 // stage^1 readers done
        if (t + 1 < ntiles) { kv_issue(t + 1, stage ^ 1); cp_wait<1>(); }
        else                { cp_wait<0>(); }
        __syncthreads();                                 // kv(t) visible

        if (t * 64 > wrow_lo + 15) continue;             // fully masked for warp

        const uint32_t kvb = sb + KV_OFF + stage * KV_STG;

        // ---- S = Q @ K^T ----
        float acc_s[8][4];
        #pragma unroll
        for (int nt = 0; nt < 8; nt++)
            #pragma unroll
            for (int i = 0; i < 4; i++) acc_s[nt][i] = 0.0f;

        #pragma unroll
        for (int kt = 0; kt < 4; kt++) {
            uint32_t kh[4][4], kl[4][4];
            const uint32_t brow = (lane & 7) + ((lane & 16) >> 1);
            const uint32_t bcol = kt * 16 + ((lane >> 3) & 1) * 8;
            #pragma unroll
            for (int g = 0; g < 4; g++) {
                const uint32_t off = (g * 16 + brow) * AROWB + bcol * 2;
                ldsm_x4(kh[g], kvb + off);
                ldsm_x4(kl[g], kvb + 64 * AROWB + off);
            }
            #pragma unroll
            for (int nt = 0; nt < 8; nt++) {
                const uint32_t* bh = &kh[nt >> 1][(nt & 1) * 2];
                const uint32_t* bl = &kl[nt >> 1][(nt & 1) * 2];
                mma16816(acc_s[nt], qhF[kt], bh);
                mma16816(acc_s[nt], qhF[kt], bl);
                mma16816(acc_s[nt], qlF[kt], bh);
            }
        }

        // ---- causal mask ----
        const int r0 = q0 + wid * 16 + (lane >> 2);
        if (t * 64 + 63 > wrow_lo) {
            #pragma unroll
            for (int nt = 0; nt < 8; nt++)
                #pragma unroll
                for (int i = 0; i < 4; i++) {
                    const int row = r0 + (i >> 1) * 8;
                    const int col = t * 64 + nt * 8 + 2 * (lane & 3) + (i & 1);
                    if (col > row) acc_s[nt][i] = -1e30f;
                }
        }

        // ---- online softmax ----
        float tmax[2] = {-1e30f, -1e30f};
        #pragma unroll
        for (int nt = 0; nt < 8; nt++)
            #pragma unroll
            for (int i = 0; i < 4; i++)
                tmax[i >> 1] = fmaxf(tmax[i >> 1], acc_s[nt][i]);
        #pragma unroll
        for (int h = 0; h < 2; h++) {
            tmax[h] = fmaxf(tmax[h], __shfl_xor_sync(0xffffffffu, tmax[h], 1));
            tmax[h] = fmaxf(tmax[h], __shfl_xor_sync(0xffffffffu, tmax[h], 2));
        }
        float nm[2], corr[2];
        #pragma unroll
        for (int h = 0; h < 2; h++) {
            nm[h]   = fmaxf(m_s[h], tmax[h]);
            corr[h] = __expf(m_s[h] - nm[h]);
            m_s[h]  = nm[h];
        }
        float psum[2] = {0.0f, 0.0f};
        #pragma unroll
        for (int nt = 0; nt < 8; nt++)
            #pragma unroll
            for (int i = 0; i < 4; i++) {
                const float p = __expf(acc_s[nt][i] - nm[i >> 1]);
                acc_s[nt][i] = p;
                psum[i >> 1] += p;
            }
        #pragma unroll
        for (int h = 0; h < 2; h++) {
            psum[h] += __shfl_xor_sync(0xffffffffu, psum[h], 1);
            psum[h] += __shfl_xor_sync(0xffffffffu, psum[h], 2);
            l_s[h] = l_s[h] * corr[h] + psum[h];
        }
        #pragma unroll
        for (int nt = 0; nt < 8; nt++)
            #pragma unroll
            for (int i = 0; i < 4; i++) acc_o[nt][i] *= corr[i >> 1];

        // ---- pack P (C-fragment -> A-fragment identity) ----
        uint32_t ph[4][4], pl[4][4];
        #pragma unroll
        for (int kt = 0; kt < 4; kt++) {
            split2(acc_s[2 * kt][0],     acc_s[2 * kt][1],     ph[kt][0], pl[kt][0]);
            split2(acc_s[2 * kt][2],     acc_s[2 * kt][3],     ph[kt][1], pl[kt][1]);
            split2(acc_s[2 * kt + 1][0], acc_s[2 * kt + 1][1], ph[kt][2], pl[kt][2]);
            split2(acc_s[2 * kt + 1][2], acc_s[2 * kt + 1][3], ph[kt][3], pl[kt][3]);
        }

        // ---- O += P @ V ----
        #pragma unroll
        for (int kt = 0; kt < 4; kt++) {
            uint32_t vh[4][4], vl[4][4];
            const uint32_t vrow = kt * 16 + (lane & 15);
            const uint32_t vcol = (lane >> 4) * 8;
            #pragma unroll
            for (int g = 0; g < 4; g++) {
                const uint32_t off = vrow * AROWB + (g * 16 + vcol) * 2;
                ldsm_x4t(vh[g], kvb + 2 * 64 * AROWB + off);
                ldsm_x4t(vl[g], kvb + 3 * 64 * AROWB + off);
            }
            #pragma unroll
            for (int nt = 0; nt < 8; nt++) {
                const uint32_t* bh = &vh[nt >> 1][(nt & 1) * 2];
                const uint32_t* bl = &vl[nt >> 1][(nt & 1) * 2];
                mma16816(acc_o[nt], ph[kt], bh);
                mma16816(acc_o[nt], pl[kt], bh);
                mma16816(acc_o[nt], ph[kt], bl);
            }
        }
    }

    // ---- epilogue: normalize, split, write row-major hi/lo ----
    const float inv0 = 1.0f / l_s[0];
    const float inv1 = 1.0f / l_s[1];
    const int b  = bh >> 4;
    const int hh = bh & 15;
    const int r0 = q0 + wid * 16 + (lane >> 2);
    #pragma unroll
    for (int nt = 0; nt < 8; nt++) {
        const int col = hh * 64 + nt * 8 + 2 * (lane & 3);
        {
            const long idx = ((long)(b * S_LEN + r0)) * DMODEL + col;
            uint32_t hi, lo;
            split2(acc_o[nt][0] * inv0, acc_o[nt][1] * inv0, hi, lo);
            *(uint32_t*)(Ohi + idx) = hi;
            *(uint32_t*)(Olo + idx) = lo;
        }
        {
            const long idx = ((long)(b * S_LEN + r0 + 8)) * DMODEL + col;
            uint32_t hi, lo;
            split2(acc_o[nt][2] * inv1, acc_o[nt][3] * inv1, hi, lo);
            *(uint32_t*)(Ohi + idx) = hi;
            *(uint32_t*)(Olo + idx) = lo;
        }
    }
}

// ============================================================================
// conversion kernels
// ============================================================================
__global__ void __launch_bounds__(256)
conv_split(const float* __restrict__ X, __nv_bfloat16* __restrict__ hi,
           __nv_bfloat16* __restrict__ lo)
{
    const int i = blockIdx.x * 256 + threadIdx.x;   // over float2
    const float2 x = ((const float2*)X)[i];
    uint32_t h, l;
    split2(x.x, x.y, h, l);
    ((uint32_t*)hi)[i] = h;
    ((uint32_t*)lo)[i] = l;
}

__global__ void __launch_bounds__(256)
conv_w(const float* __restrict__ W, __nv_bfloat16* __restrict__ hi,
       __nv_bfloat16* __restrict__ lo)
{
    __shared__ float t[32][33];
    const int tx = threadIdx.x, ty = threadIdx.y;     // (32, 8)
    const int n0 = blockIdx.x * 32, k0 = blockIdx.y * 32;
    #pragma unroll
    for (int r = 0; r < 4; r++) {
        const int k = ty + r * 8;
        t[k][tx] = W[(long)(k0 + k) * DMODEL + n0 + tx];
    }
    __syncthreads();
    #pragma unroll
    for (int r = 0; r < 4; r++) {
        const int nl = ty + r * 8;
        const float x = t[tx][nl];
        const __nv_bfloat16 h = __float2bfloat16(x);
        const long o = (long)(n0 + nl) * DMODEL + k0 + tx;
        hi[o] = h;
        lo[o] = __float2bfloat16(x - __bfloat162float(h));
    }
}

// ============================================================================
extern "C" void kernel_launch(void* const* d_in, const int* in_sizes, int n_in,
                              void* d_out, int out_size)
{
    const float* q = (const float*)d_in[0];
    const float* k = (const float*)d_in[1];
    const float* v = (const float*)d_in[2];
    const float* w[4] = { (const float*)d_in[3], (const float*)d_in[4],
                          (const float*)d_in[5], (const float*)d_in[6] };
    float* out = (float*)d_out;

    __nv_bfloat16 *ahi, *alo, *whi, *wlo;
    __nv_bfloat16 *qhi, *qlo, *khi, *klo, *vhi, *vlo, *ohi, *olo;
    cudaGetSymbolAddress((void**)&ahi, g_Ahi);
    cudaGetSymbolAddress((void**)&alo, g_Alo);
    cudaGetSymbolAddress((void**)&whi, g_Whi);
    cudaGetSymbolAddress((void**)&wlo, g_Wlo);
    cudaGetSymbolAddress((void**)&qhi, g_Qhi);
    cudaGetSymbolAddress((void**)&qlo, g_Qlo);
    cudaGetSymbolAddress((void**)&khi, g_Khi);
    cudaGetSymbolAddress((void**)&klo, g_Klo);
    cudaGetSymbolAddress((void**)&vhi, g_Vhi);
    cudaGetSymbolAddress((void**)&vlo, g_Vlo);
    cudaGetSymbolAddress((void**)&ohi, g_Ohi);
    cudaGetSymbolAddress((void**)&olo, g_Olo);

    cudaFuncSetAttribute((const void*)gemm_mma3<true>,
                         cudaFuncAttributeMaxDynamicSharedMemorySize, GSMEM);
    cudaFuncSetAttribute((const void*)gemm_mma3<false>,
                         cudaFuncAttributeMaxDynamicSharedMemorySize, GSMEM);
    cudaFuncSetAttribute((const void*)attn_mma,
                         cudaFuncAttributeMaxDynamicSharedMemorySize, ASMEM);

    const dim3 wgrid(32, 32), wblk(32, 8);
    for (int i = 0; i < 4; i++)
        conv_w<<<wgrid, wblk>>>(w[i], whi + (long)i * WELEMS, wlo + (long)i * WELEMS);

    const dim3 gg(8, 64);
    const int nConvBlocks = AELEMS / 2 / 256;

    conv_split<<<nConvBlocks, 256>>>(q, ahi, alo);
    gemm_mma3<true><<<gg, 256, GSMEM>>>(ahi, alo,
        whi + 0 * (long)WELEMS, wlo + 0 * (long)WELEMS,
        nullptr, qhi, qlo, 0.125f);
    conv_split<<<nConvBlocks, 256>>>(k, ahi, alo);
    gemm_mma3<true><<<gg, 256, GSMEM>>>(ahi, alo,
        whi + 1 * (long)WELEMS, wlo + 1 * (long)WELEMS,
        nullptr, khi, klo, 1.0f);
    conv_split<<<nConvBlocks, 256>>>(v, ahi, alo);
    gemm_mma3<true><<<gg, 256, GSMEM>>>(ahi, alo,
        whi + 2 * (long)WELEMS, wlo + 2 * (long)WELEMS,
        nullptr, vhi, vlo, 1.0f);

    attn_mma<<<dim3(S_LEN / 128, BHCNT), 256, ASMEM>>>(qhi, qlo, khi, klo,
                                                       vhi, vlo, ohi, olo);

    gemm_mma3<false><<<gg, 256, GSMEM>>>(ohi, olo,
        whi + 3 * (long)WELEMS, wlo + 3 * (long)WELEMS,
        out, nullptr, nullptr, 1.0f);
}

// round 5
// speedup vs baseline: 3.3163x; 1.0594x over previous
#include <cuda_runtime.h>
#include <cuda_bf16.h>
#include <cstdint>

#define S_LEN   2048
#define DMODEL  1024
#define NHEADS  16
#define HDIM    64
#define BATCH   4
#define BHCNT   (BATCH * NHEADS)                   // 64
#define MROWS   (BATCH * S_LEN)                    // 8192
#define HS_ELEMS (BATCH * NHEADS * S_LEN * HDIM)   // 8388608
#define AELEMS  (MROWS * DMODEL)                   // 8388608
#define WELEMS  (DMODEL * DMODEL)                  // 1048576

// ---- scratch (all bf16 hi/lo pairs) ----
__device__ __nv_bfloat16 g_Ahi[3][AELEMS];
__device__ __nv_bfloat16 g_Alo[3][AELEMS];
__device__ __nv_bfloat16 g_Whi[4][WELEMS];   // transposed [N][K]
__device__ __nv_bfloat16 g_Wlo[4][WELEMS];
__device__ __nv_bfloat16 g_Qhi[HS_ELEMS], g_Qlo[HS_ELEMS];   // head-split, pre-scaled 1/8
__device__ __nv_bfloat16 g_Khi[HS_ELEMS], g_Klo[HS_ELEMS];
__device__ __nv_bfloat16 g_Vhi[HS_ELEMS], g_Vlo[HS_ELEMS];
__device__ __nv_bfloat16 g_Ohi[AELEMS],  g_Olo[AELEMS];      // row-major [8192][1024]

// ============================================================================
// helpers (baseline PTX only)
// ============================================================================
__device__ __forceinline__ uint32_t smem_u32(const void* p) {
    uint32_t a;
    asm("{ .reg .u64 t; cvta.to.shared.u64 t, %1; cvt.u32.u64 %0, t; }"
        : "=r"(a) : "l"(p));
    return a;
}
__device__ __forceinline__ void cp_async16(uint32_t dst, const void* src) {
    asm volatile("cp.async.cg.shared.global [%0], [%1], 16;"
                 :: "r"(dst), "l"(src));
}
__device__ __forceinline__ void cp_commit() {
    asm volatile("cp.async.commit_group;");
}
template <int N>
__device__ __forceinline__ void cp_wait() {
    asm volatile("cp.async.wait_group %0;" :: "n"(N));
}
__device__ __forceinline__ void ldsm_x4(uint32_t* r, uint32_t addr) {
    asm volatile("ldmatrix.sync.aligned.m8n8.x4.shared.b16 {%0,%1,%2,%3}, [%4];"
                 : "=r"(r[0]), "=r"(r[1]), "=r"(r[2]), "=r"(r[3]) : "r"(addr));
}
__device__ __forceinline__ void ldsm_x4t(uint32_t* r, uint32_t addr) {
    asm volatile("ldmatrix.sync.aligned.m8n8.x4.trans.shared.b16 {%0,%1,%2,%3}, [%4];"
                 : "=r"(r[0]), "=r"(r[1]), "=r"(r[2]), "=r"(r[3]) : "r"(addr));
}
__device__ __forceinline__ void mma16816(float* d, const uint32_t* a,
                                         const uint32_t* b) {
    asm volatile("mma.sync.aligned.m16n8k16.row.col.f32.bf16.bf16.f32 "
                 "{%0,%1,%2,%3}, {%4,%5,%6,%7}, {%8,%9}, {%0,%1,%2,%3};"
                 : "+f"(d[0]), "+f"(d[1]), "+f"(d[2]), "+f"(d[3])
                 : "r"(a[0]), "r"(a[1]), "r"(a[2]), "r"(a[3]),
                   "r"(b[0]), "r"(b[1]));
}
__device__ __forceinline__ void split2(float a, float b,
                                       uint32_t& hi, uint32_t& lo) {
    __nv_bfloat16 ha = __float2bfloat16(a), hb = __float2bfloat16(b);
    __nv_bfloat16 la = __float2bfloat16(a - __bfloat162float(ha));
    __nv_bfloat16 lb = __float2bfloat16(b - __bfloat162float(hb));
    hi = (uint32_t)*(uint16_t*)&ha | ((uint32_t)*(uint16_t*)&hb << 16);
    lo = (uint32_t)*(uint16_t*)&la | ((uint32_t)*(uint16_t*)&lb << 16);
}

// ============================================================================
// Shared GEMM mainloop: 128x128 tile, BK=32, 8 warps, split-bf16 3-term.
// Term-major MMA ordering (acc reuse distance = 16).
// ============================================================================
#define ROWB       80
#define MAT_BYTES  (128 * ROWB)
#define STG_BYTES  (4 * MAT_BYTES)
#define GSMEM      (2 * STG_BYTES)      // 81920

__device__ __forceinline__ void gemm_core(
    const __nv_bfloat16* __restrict__ Ahi, const __nv_bfloat16* __restrict__ Alo,
    const __nv_bfloat16* __restrict__ Bhi, const __nv_bfloat16* __restrict__ Blo,
    char* smem, uint32_t sb, int tid, int bc, int br, float acc[2][8][4])
{
    const int lane   = tid & 31;
    const int wid    = tid >> 5;
    const int warp_m = wid >> 1;
    const int warp_n = wid & 1;

    auto issue = [&](int kc, int stage) {
        #pragma unroll
        for (int t = 0; t < 8; t++) {
            const int c   = tid + t * 256;
            const int mat = c >> 9;
            const int rem = c & 511;
            const int row = rem >> 2;
            const int seg = rem & 3;
            const long gcol = (long)kc * 32 + seg * 8;
            const __nv_bfloat16* g;
            if (mat == 0)      g = Ahi + (long)(br * 128 + row) * DMODEL + gcol;
            else if (mat == 1) g = Alo + (long)(br * 128 + row) * DMODEL + gcol;
            else if (mat == 2) g = Bhi + (long)(bc * 128 + row) * DMODEL + gcol;
            else               g = Blo + (long)(bc * 128 + row) * DMODEL + gcol;
            cp_async16(sb + stage * STG_BYTES + mat * MAT_BYTES
                       + row * ROWB + seg * 16, g);
        }
        cp_commit();
    };

    issue(0, 0);

    for (int kc = 0; kc < DMODEL / 32; kc++) {
        const int stage = kc & 1;
        __syncthreads();
        if (kc + 1 < DMODEL / 32) { issue(kc + 1, stage ^ 1); cp_wait<1>(); }
        else                      { cp_wait<0>(); }
        __syncthreads();

        const uint32_t base = sb + stage * STG_BYTES;

        #pragma unroll
        for (int kk = 0; kk < 2; kk++) {
            uint32_t ahi[2][4], alo[2][4];
            {
                const uint32_t arow = warp_m * 32 + (lane & 15);
                const uint32_t acol = kk * 16 + (lane >> 4) * 8;
                const uint32_t off  = arow * ROWB + acol * 2;
                ldsm_x4(ahi[0], base + off);
                ldsm_x4(ahi[1], base + off + 16 * ROWB);
                ldsm_x4(alo[0], base + MAT_BYTES + off);
                ldsm_x4(alo[1], base + MAT_BYTES + off + 16 * ROWB);
            }
            uint32_t bhi[4][4], blo[4][4];
            {
                const uint32_t brow = warp_n * 64 + (lane & 7) + ((lane & 16) >> 1);
                const uint32_t bcol = kk * 16 + ((lane >> 3) & 1) * 8;
                const uint32_t off  = brow * ROWB + bcol * 2;
                #pragma unroll
                for (int q = 0; q < 4; q++) {
                    ldsm_x4(bhi[q], base + 2 * MAT_BYTES + off + q * 16 * ROWB);
                    ldsm_x4(blo[q], base + 3 * MAT_BYTES + off + q * 16 * ROWB);
                }
            }
            // term-major: all 16 tiles of (hi,hi), then (hi,lo), then (lo,hi)
            #pragma unroll
            for (int mt = 0; mt < 2; mt++)
                #pragma unroll
                for (int nt = 0; nt < 8; nt++)
                    mma16816(acc[mt][nt], ahi[mt], &bhi[nt >> 1][(nt & 1) * 2]);
            #pragma unroll
            for (int mt = 0; mt < 2; mt++)
                #pragma unroll
                for (int nt = 0; nt < 8; nt++)
                    mma16816(acc[mt][nt], ahi[mt], &blo[nt >> 1][(nt & 1) * 2]);
            #pragma unroll
            for (int mt = 0; mt < 2; mt++)
                #pragma unroll
                for (int nt = 0; nt < 8; nt++)
                    mma16816(acc[mt][nt], alo[mt], &bhi[nt >> 1][(nt & 1) * 2]);
        }
    }
}

// ============================================================================
// Batched QKV projection GEMM: grid (8, 64, 3); z selects input/weight/output.
// Output: bf16 hi/lo, head-split [bh][s][d]; Q pre-scaled by 1/8.
// ============================================================================
__global__ void __launch_bounds__(256, 1)
gemm_qkv(__nv_bfloat16* __restrict__ Qhi, __nv_bfloat16* __restrict__ Qlo,
         __nv_bfloat16* __restrict__ Khi, __nv_bfloat16* __restrict__ Klo,
         __nv_bfloat16* __restrict__ Vhi, __nv_bfloat16* __restrict__ Vlo)
{
    extern __shared__ char smem[];
    const uint32_t sb = smem_u32(smem);
    const int tid = threadIdx.x;
    const int bc = blockIdx.x, br = blockIdx.y, z = blockIdx.z;

    __nv_bfloat16 *Chi, *Clo;
    float scale;
    if (z == 0)      { Chi = Qhi; Clo = Qlo; scale = 0.125f; }
    else if (z == 1) { Chi = Khi; Clo = Klo; scale = 1.0f; }
    else             { Chi = Vhi; Clo = Vlo; scale = 1.0f; }

    float acc[2][8][4];
    #pragma unroll
    for (int mt = 0; mt < 2; mt++)
        #pragma unroll
        for (int nt = 0; nt < 8; nt++)
            #pragma unroll
            for (int i = 0; i < 4; i++) acc[mt][nt][i] = 0.0f;

    gemm_core(g_Ahi[z], g_Alo[z], g_Whi[z], g_Wlo[z], smem, sb, tid, bc, br, acc);

    const int lane = tid & 31, wid = tid >> 5;
    const int warp_m = wid >> 1, warp_n = wid & 1;
    #pragma unroll
    for (int mt = 0; mt < 2; mt++) {
        #pragma unroll
        for (int nt = 0; nt < 8; nt++) {
            const int row0 = br * 128 + warp_m * 32 + mt * 16 + (lane >> 2);
            const int col  = bc * 128 + warp_n * 64 + nt * 8 + (lane & 3) * 2;
            const int h = col >> 6, dd = col & 63;
            #pragma unroll
            for (int half = 0; half < 2; half++) {
                const int r = row0 + half * 8;
                const int b = r >> 11, s = r & 2047;
                const long off = ((((long)b * NHEADS + h) * S_LEN + s) * HDIM) + dd;
                uint32_t hi, lo;
                split2(acc[mt][nt][half * 2] * scale,
                       acc[mt][nt][half * 2 + 1] * scale, hi, lo);
                *(uint32_t*)(Chi + off) = hi;
                *(uint32_t*)(Clo + off) = lo;
            }
        }
    }
}

// ============================================================================
// Output projection GEMM: fp32 row-major result.
// ============================================================================
__global__ void __launch_bounds__(256, 1)
gemm_out(const __nv_bfloat16* __restrict__ Ahi, const __nv_bfloat16* __restrict__ Alo,
         const __nv_bfloat16* __restrict__ Bhi, const __nv_bfloat16* __restrict__ Blo,
         float* __restrict__ Cf)
{
    extern __shared__ char smem[];
    const uint32_t sb = smem_u32(smem);
    const int tid = threadIdx.x;
    const int bc = blockIdx.x, br = blockIdx.y;

    float acc[2][8][4];
    #pragma unroll
    for (int mt = 0; mt < 2; mt++)
        #pragma unroll
        for (int nt = 0; nt < 8; nt++)
            #pragma unroll
            for (int i = 0; i < 4; i++) acc[mt][nt][i] = 0.0f;

    gemm_core(Ahi, Alo, Bhi, Blo, smem, sb, tid, bc, br, acc);

    const int lane = tid & 31, wid = tid >> 5;
    const int warp_m = wid >> 1, warp_n = wid & 1;
    #pragma unroll
    for (int mt = 0; mt < 2; mt++) {
        #pragma unroll
        for (int nt = 0; nt < 8; nt++) {
            const int row0 = br * 128 + warp_m * 32 + mt * 16 + (lane >> 2);
            const int col  = bc * 128 + warp_n * 64 + nt * 8 + (lane & 3) * 2;
            float2 v01; v01.x = acc[mt][nt][0]; v01.y = acc[mt][nt][1];
            float2 v23; v23.x = acc[mt][nt][2]; v23.y = acc[mt][nt][3];
            *(float2*)&Cf[(long)row0 * DMODEL + col] = v01;
            *(float2*)&Cf[(long)(row0 + 8) * DMODEL + col] = v23;
        }
    }
}

// ============================================================================
// Tensor-core causal flash attention (split-bf16 3-term), term-major MMAs.
// ============================================================================
#define AROWB   144
#define QH_OFF  0
#define QL_OFF  (128 * AROWB)
#define KV_OFF  (2 * 128 * AROWB)
#define KV_STG  (4 * 64 * AROWB)
#define ASMEM   (KV_OFF + 2 * KV_STG)   // 110592

__global__ void __launch_bounds__(256, 1)
attn_mma(const __nv_bfloat16* __restrict__ Qhi, const __nv_bfloat16* __restrict__ Qlo,
         const __nv_bfloat16* __restrict__ Khi, const __nv_bfloat16* __restrict__ Klo,
         const __nv_bfloat16* __restrict__ Vhi, const __nv_bfloat16* __restrict__ Vlo,
         __nv_bfloat16* __restrict__ Ohi, __nv_bfloat16* __restrict__ Olo)
{
    extern __shared__ char smem[];
    const uint32_t sb = smem_u32(smem);
    const int tid = threadIdx.x, wid = tid >> 5, lane = tid & 31;
    const int q0 = blockIdx.x * 128;
    const int bh = blockIdx.y;
    const long base = (long)bh * S_LEN * HDIM;

    {
        #pragma unroll
        for (int t = 0; t < 8; t++) {
            const int c = tid + t * 256;
            const int arr = c >> 10, rem = c & 1023;
            const int row = rem >> 3, seg = rem & 7;
            const __nv_bfloat16* src = (arr ? Qlo : Qhi)
                                     + base + (long)(q0 + row) * HDIM + seg * 8;
            cp_async16(sb + (arr ? QL_OFF : QH_OFF) + row * AROWB + seg * 16, src);
        }
        cp_commit();
    }

    const int ntiles = blockIdx.x * 2 + 2;

    auto kv_issue = [&](int t, int stage) {
        #pragma unroll
        for (int i = 0; i < 8; i++) {
            const int c = tid + i * 256;
            const int arr = c >> 9, rem = c & 511;
            const int row = rem >> 3, seg = rem & 7;
            const __nv_bfloat16* p;
            if (arr == 0)      p = Khi;
            else if (arr == 1) p = Klo;
            else if (arr == 2) p = Vhi;
            else               p = Vlo;
            cp_async16(sb + KV_OFF + stage * KV_STG + arr * (64 * AROWB)
                       + row * AROWB + seg * 16,
                       p + base + (long)(t * 64 + row) * HDIM + seg * 8);
        }
        cp_commit();
    };

    kv_issue(0, 0);
    cp_wait<1>();
    __syncthreads();

    uint32_t qhF[4][4], qlF[4][4];
    {
        const uint32_t arow = wid * 16 + (lane & 15);
        #pragma unroll
        for (int kt = 0; kt < 4; kt++) {
            const uint32_t off = arow * AROWB + (kt * 16 + (lane >> 4) * 8) * 2;
            ldsm_x4(qhF[kt], sb + QH_OFF + off);
            ldsm_x4(qlF[kt], sb + QL_OFF + off);
        }
    }

    float m_s[2] = {-1e30f, -1e30f};
    float l_s[2] = {0.0f, 0.0f};
    float acc_o[8][4];
    #pragma unroll
    for (int nt = 0; nt < 8; nt++)
        #pragma unroll
        for (int i = 0; i < 4; i++) acc_o[nt][i] = 0.0f;

    const int wrow_lo = q0 + wid * 16;

    for (int t = 0; t < ntiles; t++) {
        const int stage = t & 1;
        __syncthreads();
        if (t + 1 < ntiles) { kv_issue(t + 1, stage ^ 1); cp_wait<1>(); }
        else                { cp_wait<0>(); }
        __syncthreads();

        if (t * 64 > wrow_lo + 15) continue;

        const uint32_t kvb = sb + KV_OFF + stage * KV_STG;

        // ---- S = Q @ K^T (term-major per kt) ----
        float acc_s[8][4];
        #pragma unroll
        for (int nt = 0; nt < 8; nt++)
            #pragma unroll
            for (int i = 0; i < 4; i++) acc_s[nt][i] = 0.0f;

        #pragma unroll
        for (int kt = 0; kt < 4; kt++) {
            uint32_t kh[4][4], kl[4][4];
            const uint32_t brow = (lane & 7) + ((lane & 16) >> 1);
            const uint32_t bcol = kt * 16 + ((lane >> 3) & 1) * 8;
            #pragma unroll
            for (int g = 0; g < 4; g++) {
                const uint32_t off = (g * 16 + brow) * AROWB + bcol * 2;
                ldsm_x4(kh[g], kvb + off);
                ldsm_x4(kl[g], kvb + 64 * AROWB + off);
            }
            #pragma unroll
            for (int nt = 0; nt < 8; nt++)
                mma16816(acc_s[nt], qhF[kt], &kh[nt >> 1][(nt & 1) * 2]);
            #pragma unroll
            for (int nt = 0; nt < 8; nt++)
                mma16816(acc_s[nt], qhF[kt], &kl[nt >> 1][(nt & 1) * 2]);
            #pragma unroll
            for (int nt = 0; nt < 8; nt++)
                mma16816(acc_s[nt], qlF[kt], &kh[nt >> 1][(nt & 1) * 2]);
        }

        // ---- causal mask ----
        const int r0 = q0 + wid * 16 + (lane >> 2);
        if (t * 64 + 63 > wrow_lo) {
            #pragma unroll
            for (int nt = 0; nt < 8; nt++)
                #pragma unroll
                for (int i = 0; i < 4; i++) {
                    const int row = r0 + (i >> 1) * 8;
                    const int col = t * 64 + nt * 8 + 2 * (lane & 3) + (i & 1);
                    if (col > row) acc_s[nt][i] = -1e30f;
                }
        }

        // ---- online softmax ----
        float tmax[2] = {-1e30f, -1e30f};
        #pragma unroll
        for (int nt = 0; nt < 8; nt++)
            #pragma unroll
            for (int i = 0; i < 4; i++)
                tmax[i >> 1] = fmaxf(tmax[i >> 1], acc_s[nt][i]);
        #pragma unroll
        for (int h = 0; h < 2; h++) {
            tmax[h] = fmaxf(tmax[h], __shfl_xor_sync(0xffffffffu, tmax[h], 1));
            tmax[h] = fmaxf(tmax[h], __shfl_xor_sync(0xffffffffu, tmax[h], 2));
        }
        float nm[2], corr[2];
        #pragma unroll
        for (int h = 0; h < 2; h++) {
            nm[h]   = fmaxf(m_s[h], tmax[h]);
            corr[h] = __expf(m_s[h] - nm[h]);
            m_s[h]  = nm[h];
        }
        float psum[2] = {0.0f, 0.0f};
        #pragma unroll
        for (int nt = 0; nt < 8; nt++)
            #pragma unroll
            for (int i = 0; i < 4; i++) {
                const float p = __expf(acc_s[nt][i] - nm[i >> 1]);
                acc_s[nt][i] = p;
                psum[i >> 1] += p;
            }
        #pragma unroll
        for (int h = 0; h < 2; h++) {
            psum[h] += __shfl_xor_sync(0xffffffffu, psum[h], 1);
            psum[h] += __shfl_xor_sync(0xffffffffu, psum[h], 2);
            l_s[h] = l_s[h] * corr[h] + psum[h];
        }
        #pragma unroll
        for (int nt = 0; nt < 8; nt++)
            #pragma unroll
            for (int i = 0; i < 4; i++) acc_o[nt][i] *= corr[i >> 1];

        // ---- pack P ----
        uint32_t ph[4][4], pl[4][4];
        #pragma unroll
        for (int kt = 0; kt < 4; kt++) {
            split2(acc_s[2 * kt][0],     acc_s[2 * kt][1],     ph[kt][0], pl[kt][0]);
            split2(acc_s[2 * kt][2],     acc_s[2 * kt][3],     ph[kt][1], pl[kt][1]);
            split2(acc_s[2 * kt + 1][0], acc_s[2 * kt + 1][1], ph[kt][2], pl[kt][2]);
            split2(acc_s[2 * kt + 1][2], acc_s[2 * kt + 1][3], ph[kt][3], pl[kt][3]);
        }

        // ---- O += P @ V (term-major per kt) ----
        #pragma unroll
        for (int kt = 0; kt < 4; kt++) {
            uint32_t vh[4][4], vl[4][4];
            const uint32_t vrow = kt * 16 + (lane & 15);
            const uint32_t vcol = (lane >> 4) * 8;
            #pragma unroll
            for (int g = 0; g < 4; g++) {
                const uint32_t off = vrow * AROWB + (g * 16 + vcol) * 2;
                ldsm_x4t(vh[g], kvb + 2 * 64 * AROWB + off);
                ldsm_x4t(vl[g], kvb + 3 * 64 * AROWB + off);
            }
            #pragma unroll
            for (int nt = 0; nt < 8; nt++)
                mma16816(acc_o[nt], ph[kt], &vh[nt >> 1][(nt & 1) * 2]);
            #pragma unroll
            for (int nt = 0; nt < 8; nt++)
                mma16816(acc_o[nt], pl[kt], &vh[nt >> 1][(nt & 1) * 2]);
            #pragma unroll
            for (int nt = 0; nt < 8; nt++)
                mma16816(acc_o[nt], ph[kt], &vl[nt >> 1][(nt & 1) * 2]);
        }
    }

    // ---- epilogue ----
    const float inv0 = 1.0f / l_s[0];
    const float inv1 = 1.0f / l_s[1];
    const int b  = bh >> 4;
    const int hh = bh & 15;
    const int r0 = q0 + wid * 16 + (lane >> 2);
    #pragma unroll
    for (int nt = 0; nt < 8; nt++) {
        const int col = hh * 64 + nt * 8 + 2 * (lane & 3);
        {
            const long idx = ((long)(b * S_LEN + r0)) * DMODEL + col;
            uint32_t hi, lo;
            split2(acc_o[nt][0] * inv0, acc_o[nt][1] * inv0, hi, lo);
            *(uint32_t*)(Ohi + idx) = hi;
            *(uint32_t*)(Olo + idx) = lo;
        }
        {
            const long idx = ((long)(b * S_LEN + r0 + 8)) * DMODEL + col;
            uint32_t hi, lo;
            split2(acc_o[nt][2] * inv1, acc_o[nt][3] * inv1, hi, lo);
            *(uint32_t*)(Ohi + idx) = hi;
            *(uint32_t*)(Olo + idx) = lo;
        }
    }
}

// ============================================================================
// conversion kernels (fused)
// ============================================================================
__global__ void __launch_bounds__(256)
conv_qkv(const float* __restrict__ q, const float* __restrict__ k,
         const float* __restrict__ v)
{
    const int z = blockIdx.y;
    const float* X = (z == 0) ? q : (z == 1) ? k : v;
    const int i = blockIdx.x * 256 + threadIdx.x;   // over float2
    const float2 x = ((const float2*)X)[i];
    uint32_t h, l;
    split2(x.x, x.y, h, l);
    ((uint32_t*)g_Ahi[z])[i] = h;
    ((uint32_t*)g_Alo[z])[i] = l;
}

__global__ void __launch_bounds__(256)
conv_w(const float* __restrict__ W0, const float* __restrict__ W1,
       const float* __restrict__ W2, const float* __restrict__ W3)
{
    __shared__ float t[32][33];
    const int z = blockIdx.z;
    const float* W = (z == 0) ? W0 : (z == 1) ? W1 : (z == 2) ? W2 : W3;
    const int tx = threadIdx.x, ty = threadIdx.y;     // (32, 8)
    const int n0 = blockIdx.x * 32, k0 = blockIdx.y * 32;
    #pragma unroll
    for (int r = 0; r < 4; r++) {
        const int k = ty + r * 8;
        t[k][tx] = W[(long)(k0 + k) * DMODEL + n0 + tx];
    }
    __syncthreads();
    #pragma unroll
    for (int r = 0; r < 4; r++) {
        const int nl = ty + r * 8;
        const float x = t[tx][nl];
        const __nv_bfloat16 h = __float2bfloat16(x);
        const long o = (long)(n0 + nl) * DMODEL + k0 + tx;
        g_Whi[z][o] = h;
        g_Wlo[z][o] = __float2bfloat16(x - __bfloat162float(h));
    }
}

// ============================================================================
extern "C" void kernel_launch(void* const* d_in, const int* in_sizes, int n_in,
                              void* d_out, int out_size)
{
    const float* q = (const float*)d_in[0];
    const float* k = (const float*)d_in[1];
    const float* v = (const float*)d_in[2];
    float* out = (float*)d_out;

    __nv_bfloat16 *whi, *wlo;
    __nv_bfloat16 *qhi, *qlo, *khi, *klo, *vhi, *vlo, *ohi, *olo;
    cudaGetSymbolAddress((void**)&whi, g_Whi);
    cudaGetSymbolAddress((void**)&wlo, g_Wlo);
    cudaGetSymbolAddress((void**)&qhi, g_Qhi);
    cudaGetSymbolAddress((void**)&qlo, g_Qlo);
    cudaGetSymbolAddress((void**)&khi, g_Khi);
    cudaGetSymbolAddress((void**)&klo, g_Klo);
    cudaGetSymbolAddress((void**)&vhi, g_Vhi);
    cudaGetSymbolAddress((void**)&vlo, g_Vlo);
    cudaGetSymbolAddress((void**)&ohi, g_Ohi);
    cudaGetSymbolAddress((void**)&olo, g_Olo);

    cudaFuncSetAttribute((const void*)gemm_qkv,
                         cudaFuncAttributeMaxDynamicSharedMemorySize, GSMEM);
    cudaFuncSetAttribute((const void*)gemm_out,
                         cudaFuncAttributeMaxDynamicSharedMemorySize, GSMEM);
    cudaFuncSetAttribute((const void*)attn_mma,
                         cudaFuncAttributeMaxDynamicSharedMemorySize, ASMEM);

    conv_w<<<dim3(32, 32, 4), dim3(32, 8)>>>(
        (const float*)d_in[3], (const float*)d_in[4],
        (const float*)d_in[5], (const float*)d_in[6]);

    conv_qkv<<<dim3(AELEMS / 2 / 256, 3), 256>>>(q, k, v);

    gemm_qkv<<<dim3(8, 64, 3), 256, GSMEM>>>(qhi, qlo, khi, klo, vhi, vlo);

    attn_mma<<<dim3(S_LEN / 128, BHCNT), 256, ASMEM>>>(qhi, qlo, khi, klo,
                                                       vhi, vlo, ohi, olo);

    gemm_out<<<dim3(8, 64), 256, GSMEM>>>(ohi, olo,
        whi + 3 * (long)WELEMS, wlo + 3 * (long)WELEMS, out);
}

// round 6
// speedup vs baseline: 3.3440x; 1.0083x over previous
#include <cuda_runtime.h>
#include <cuda_bf16.h>
#include <cstdint>

#define S_LEN   2048
#define DMODEL  1024
#define NHEADS  16
#define HDIM    64
#define BATCH   4
#define BHCNT   (BATCH * NHEADS)                   // 64
#define MROWS   (BATCH * S_LEN)                    // 8192
#define HS_ELEMS (BATCH * NHEADS * S_LEN * HDIM)   // 8388608
#define AELEMS  (MROWS * DMODEL)                   // 8388608
#define WELEMS  (DMODEL * DMODEL)                  // 1048576

// ---- scratch (all bf16 hi/lo pairs) ----
__device__ __nv_bfloat16 g_Ahi[3][AELEMS];
__device__ __nv_bfloat16 g_Alo[3][AELEMS];
__device__ __nv_bfloat16 g_Whi[4][WELEMS];   // transposed [N][K]
__device__ __nv_bfloat16 g_Wlo[4][WELEMS];
__device__ __nv_bfloat16 g_Qhi[HS_ELEMS], g_Qlo[HS_ELEMS];   // head-split, pre-scaled 1/8
__device__ __nv_bfloat16 g_Khi[HS_ELEMS], g_Klo[HS_ELEMS];
__device__ __nv_bfloat16 g_Vhi[HS_ELEMS], g_Vlo[HS_ELEMS];
__device__ __nv_bfloat16 g_Ohi[AELEMS],  g_Olo[AELEMS];      // row-major [8192][1024]

// ============================================================================
// helpers (baseline PTX only)
// ============================================================================
__device__ __forceinline__ uint32_t smem_u32(const void* p) {
    uint32_t a;
    asm("{ .reg .u64 t; cvta.to.shared.u64 t, %1; cvt.u32.u64 %0, t; }"
        : "=r"(a) : "l"(p));
    return a;
}
__device__ __forceinline__ void cp_async16(uint32_t dst, const void* src) {
    asm volatile("cp.async.cg.shared.global [%0], [%1], 16;"
                 :: "r"(dst), "l"(src));
}
__device__ __forceinline__ void cp_commit() {
    asm volatile("cp.async.commit_group;");
}
template <int N>
__device__ __forceinline__ void cp_wait() {
    asm volatile("cp.async.wait_group %0;" :: "n"(N));
}
__device__ __forceinline__ void ldsm_x4(uint32_t* r, uint32_t addr) {
    asm volatile("ldmatrix.sync.aligned.m8n8.x4.shared.b16 {%0,%1,%2,%3}, [%4];"
                 : "=r"(r[0]), "=r"(r[1]), "=r"(r[2]), "=r"(r[3]) : "r"(addr));
}
__device__ __forceinline__ void ldsm_x4t(uint32_t* r, uint32_t addr) {
    asm volatile("ldmatrix.sync.aligned.m8n8.x4.trans.shared.b16 {%0,%1,%2,%3}, [%4];"
                 : "=r"(r[0]), "=r"(r[1]), "=r"(r[2]), "=r"(r[3]) : "r"(addr));
}
__device__ __forceinline__ void mma16816(float* d, const uint32_t* a,
                                         const uint32_t* b) {
    asm volatile("mma.sync.aligned.m16n8k16.row.col.f32.bf16.bf16.f32 "
                 "{%0,%1,%2,%3}, {%4,%5,%6,%7}, {%8,%9}, {%0,%1,%2,%3};"
                 : "+f"(d[0]), "+f"(d[1]), "+f"(d[2]), "+f"(d[3])
                 : "r"(a[0]), "r"(a[1]), "r"(a[2]), "r"(a[3]),
                   "r"(b[0]), "r"(b[1]));
}
__device__ __forceinline__ void split2(float a, float b,
                                       uint32_t& hi, uint32_t& lo) {
    __nv_bfloat16 ha = __float2bfloat16(a), hb = __float2bfloat16(b);
    __nv_bfloat16 la = __float2bfloat16(a - __bfloat162float(ha));
    __nv_bfloat16 lb = __float2bfloat16(b - __bfloat162float(hb));
    hi = (uint32_t)*(uint16_t*)&ha | ((uint32_t)*(uint16_t*)&hb << 16);
    lo = (uint32_t)*(uint16_t*)&la | ((uint32_t)*(uint16_t*)&lb << 16);
}

// ============================================================================
// Shared GEMM mainloop: 128x128 tile, BK=32, 8 warps, split-bf16 3-term.
// 3-stage cp.async pipeline, ONE __syncthreads per K-chunk.
// ============================================================================
#define ROWB       80
#define MAT_BYTES  (128 * ROWB)
#define STG_BYTES  (4 * MAT_BYTES)
#define GSMEM      (3 * STG_BYTES)      // 122880

__device__ __forceinline__ void gemm_core(
    const __nv_bfloat16* __restrict__ Ahi, const __nv_bfloat16* __restrict__ Alo,
    const __nv_bfloat16* __restrict__ Bhi, const __nv_bfloat16* __restrict__ Blo,
    char* smem, uint32_t sb, int tid, int bc, int br, float acc[2][8][4])
{
    const int lane   = tid & 31;
    const int wid    = tid >> 5;
    const int warp_m = wid >> 1;
    const int warp_n = wid & 1;

    auto issue = [&](int kc, int stage) {
        #pragma unroll
        for (int t = 0; t < 8; t++) {
            const int c   = tid + t * 256;
            const int mat = c >> 9;
            const int rem = c & 511;
            const int row = rem >> 2;
            const int seg = rem & 3;
            const long gcol = (long)kc * 32 + seg * 8;
            const __nv_bfloat16* g;
            if (mat == 0)      g = Ahi + (long)(br * 128 + row) * DMODEL + gcol;
            else if (mat == 1) g = Alo + (long)(br * 128 + row) * DMODEL + gcol;
            else if (mat == 2) g = Bhi + (long)(bc * 128 + row) * DMODEL + gcol;
            else               g = Blo + (long)(bc * 128 + row) * DMODEL + gcol;
            cp_async16(sb + stage * STG_BYTES + mat * MAT_BYTES
                       + row * ROWB + seg * 16, g);
        }
        cp_commit();
    };

    issue(0, 0);
    issue(1, 1);

    const int NKC = DMODEL / 32;         // 32
    int st = 0, st_n2 = 2;               // stage of kc, stage of kc+2
    for (int kc = 0; kc < NKC; kc++) {
        if (kc + 1 < NKC) cp_wait<1>(); else cp_wait<0>();
        __syncthreads();                 // stage st visible; stage st_n2 free
        if (kc + 2 < NKC) issue(kc + 2, st_n2);

        const uint32_t base = sb + st * STG_BYTES;

        #pragma unroll
        for (int kk = 0; kk < 2; kk++) {
            uint32_t ahi[2][4], alo[2][4];
            {
                const uint32_t arow = warp_m * 32 + (lane & 15);
                const uint32_t acol = kk * 16 + (lane >> 4) * 8;
                const uint32_t off  = arow * ROWB + acol * 2;
                ldsm_x4(ahi[0], base + off);
                ldsm_x4(ahi[1], base + off + 16 * ROWB);
                ldsm_x4(alo[0], base + MAT_BYTES + off);
                ldsm_x4(alo[1], base + MAT_BYTES + off + 16 * ROWB);
            }
            uint32_t bhi[4][4], blo[4][4];
            {
                const uint32_t brow = warp_n * 64 + (lane & 7) + ((lane & 16) >> 1);
                const uint32_t bcol = kk * 16 + ((lane >> 3) & 1) * 8;
                const uint32_t off  = brow * ROWB + bcol * 2;
                #pragma unroll
                for (int q = 0; q < 4; q++) {
                    ldsm_x4(bhi[q], base + 2 * MAT_BYTES + off + q * 16 * ROWB);
                    ldsm_x4(blo[q], base + 3 * MAT_BYTES + off + q * 16 * ROWB);
                }
            }
            #pragma unroll
            for (int mt = 0; mt < 2; mt++)
                #pragma unroll
                for (int nt = 0; nt < 8; nt++)
                    mma16816(acc[mt][nt], ahi[mt], &bhi[nt >> 1][(nt & 1) * 2]);
            #pragma unroll
            for (int mt = 0; mt < 2; mt++)
                #pragma unroll
                for (int nt = 0; nt < 8; nt++)
                    mma16816(acc[mt][nt], ahi[mt], &blo[nt >> 1][(nt & 1) * 2]);
            #pragma unroll
            for (int mt = 0; mt < 2; mt++)
                #pragma unroll
                for (int nt = 0; nt < 8; nt++)
                    mma16816(acc[mt][nt], alo[mt], &bhi[nt >> 1][(nt & 1) * 2]);
        }

        st = (st == 2) ? 0 : st + 1;
        st_n2 = (st_n2 == 2) ? 0 : st_n2 + 1;
    }
}

// ============================================================================
// Batched QKV projection GEMM: grid (8, 64, 3).
// ============================================================================
__global__ void __launch_bounds__(256, 1)
gemm_qkv(__nv_bfloat16* __restrict__ Qhi, __nv_bfloat16* __restrict__ Qlo,
         __nv_bfloat16* __restrict__ Khi, __nv_bfloat16* __restrict__ Klo,
         __nv_bfloat16* __restrict__ Vhi, __nv_bfloat16* __restrict__ Vlo)
{
    extern __shared__ char smem[];
    const uint32_t sb = smem_u32(smem);
    const int tid = threadIdx.x;
    const int bc = blockIdx.x, br = blockIdx.y, z = blockIdx.z;

    __nv_bfloat16 *Chi, *Clo;
    float scale;
    if (z == 0)      { Chi = Qhi; Clo = Qlo; scale = 0.125f; }
    else if (z == 1) { Chi = Khi; Clo = Klo; scale = 1.0f; }
    else             { Chi = Vhi; Clo = Vlo; scale = 1.0f; }

    float acc[2][8][4];
    #pragma unroll
    for (int mt = 0; mt < 2; mt++)
        #pragma unroll
        for (int nt = 0; nt < 8; nt++)
            #pragma unroll
            for (int i = 0; i < 4; i++) acc[mt][nt][i] = 0.0f;

    gemm_core(g_Ahi[z], g_Alo[z], g_Whi[z], g_Wlo[z], smem, sb, tid, bc, br, acc);

    const int lane = tid & 31, wid = tid >> 5;
    const int warp_m = wid >> 1, warp_n = wid & 1;
    #pragma unroll
    for (int mt = 0; mt < 2; mt++) {
        #pragma unroll
        for (int nt = 0; nt < 8; nt++) {
            const int row0 = br * 128 + warp_m * 32 + mt * 16 + (lane >> 2);
            const int col  = bc * 128 + warp_n * 64 + nt * 8 + (lane & 3) * 2;
            const int h = col >> 6, dd = col & 63;
            #pragma unroll
            for (int half = 0; half < 2; half++) {
                const int r = row0 + half * 8;
                const int b = r >> 11, s = r & 2047;
                const long off = ((((long)b * NHEADS + h) * S_LEN + s) * HDIM) + dd;
                uint32_t hi, lo;
                split2(acc[mt][nt][half * 2] * scale,
                       acc[mt][nt][half * 2 + 1] * scale, hi, lo);
                *(uint32_t*)(Chi + off) = hi;
                *(uint32_t*)(Clo + off) = lo;
            }
        }
    }
}

// ============================================================================
// Output projection GEMM: fp32 row-major result.
// ============================================================================
__global__ void __launch_bounds__(256, 1)
gemm_out(const __nv_bfloat16* __restrict__ Ahi, const __nv_bfloat16* __restrict__ Alo,
         const __nv_bfloat16* __restrict__ Bhi, const __nv_bfloat16* __restrict__ Blo,
         float* __restrict__ Cf)
{
    extern __shared__ char smem[];
    const uint32_t sb = smem_u32(smem);
    const int tid = threadIdx.x;
    const int bc = blockIdx.x, br = blockIdx.y;

    float acc[2][8][4];
    #pragma unroll
    for (int mt = 0; mt < 2; mt++)
        #pragma unroll
        for (int nt = 0; nt < 8; nt++)
            #pragma unroll
            for (int i = 0; i < 4; i++) acc[mt][nt][i] = 0.0f;

    gemm_core(Ahi, Alo, Bhi, Blo, smem, sb, tid, bc, br, acc);

    const int lane = tid & 31, wid = tid >> 5;
    const int warp_m = wid >> 1, warp_n = wid & 1;
    #pragma unroll
    for (int mt = 0; mt < 2; mt++) {
        #pragma unroll
        for (int nt = 0; nt < 8; nt++) {
            const int row0 = br * 128 + warp_m * 32 + mt * 16 + (lane >> 2);
            const int col  = bc * 128 + warp_n * 64 + nt * 8 + (lane & 3) * 2;
            float2 v01; v01.x = acc[mt][nt][0]; v01.y = acc[mt][nt][1];
            float2 v23; v23.x = acc[mt][nt][2]; v23.y = acc[mt][nt][3];
            *(float2*)&Cf[(long)row0 * DMODEL + col] = v01;
            *(float2*)&Cf[(long)(row0 + 8) * DMODEL + col] = v23;
        }
    }
}

// ============================================================================
// Tensor-core causal flash attention (split-bf16 3-term), term-major MMAs,
// 3-stage KV pipeline (1 sync/tile), vanishing-tile skip.
// ============================================================================
#define AROWB   144
#define QH_OFF  0
#define QL_OFF  (128 * AROWB)
#define KV_OFF  (2 * 128 * AROWB)
#define KV_STG  (4 * 64 * AROWB)
#define ASMEM   (KV_OFF + 3 * KV_STG)   // 147456

__global__ void __launch_bounds__(256, 1)
attn_mma(const __nv_bfloat16* __restrict__ Qhi, const __nv_bfloat16* __restrict__ Qlo,
         const __nv_bfloat16* __restrict__ Khi, const __nv_bfloat16* __restrict__ Klo,
         const __nv_bfloat16* __restrict__ Vhi, const __nv_bfloat16* __restrict__ Vlo,
         __nv_bfloat16* __restrict__ Ohi, __nv_bfloat16* __restrict__ Olo)
{
    extern __shared__ char smem[];
    const uint32_t sb = smem_u32(smem);
    const int tid = threadIdx.x, wid = tid >> 5, lane = tid & 31;
    const int q0 = blockIdx.x * 128;
    const int bh = blockIdx.y;
    const long base = (long)bh * S_LEN * HDIM;

    // ---- Q load (own cp.async group) ----
    {
        #pragma unroll
        for (int t = 0; t < 8; t++) {
            const int c = tid + t * 256;
            const int arr = c >> 10, rem = c & 1023;
            const int row = rem >> 3, seg = rem & 7;
            const __nv_bfloat16* src = (arr ? Qlo : Qhi)
                                     + base + (long)(q0 + row) * HDIM + seg * 8;
            cp_async16(sb + (arr ? QL_OFF : QH_OFF) + row * AROWB + seg * 16, src);
        }
        cp_commit();
    }

    const int ntiles = blockIdx.x * 2 + 2;   // >= 2

    auto kv_issue = [&](int t, int stage) {
        #pragma unroll
        for (int i = 0; i < 8; i++) {
            const int c = tid + i * 256;
            const int arr = c >> 9, rem = c & 511;
            const int row = rem >> 3, seg = rem & 7;
            const __nv_bfloat16* p;
            if (arr == 0)      p = Khi;
            else if (arr == 1) p = Klo;
            else if (arr == 2) p = Vhi;
            else               p = Vlo;
            cp_async16(sb + KV_OFF + stage * KV_STG + arr * (64 * AROWB)
                       + row * AROWB + seg * 16,
                       p + base + (long)(t * 64 + row) * HDIM + seg * 8);
        }
        cp_commit();
    };

    kv_issue(0, 0);
    kv_issue(1, 1);
    cp_wait<2>();            // Q resident
    __syncthreads();

    uint32_t qhF[4][4], qlF[4][4];
    {
        const uint32_t arow = wid * 16 + (lane & 15);
        #pragma unroll
        for (int kt = 0; kt < 4; kt++) {
            const uint32_t off = arow * AROWB + (kt * 16 + (lane >> 4) * 8) * 2;
            ldsm_x4(qhF[kt], sb + QH_OFF + off);
            ldsm_x4(qlF[kt], sb + QL_OFF + off);
        }
    }

    float m_s[2] = {-1e30f, -1e30f};
    float l_s[2] = {0.0f, 0.0f};
    float acc_o[8][4];
    #pragma unroll
    for (int nt = 0; nt < 8; nt++)
        #pragma unroll
        for (int i = 0; i < 4; i++) acc_o[nt][i] = 0.0f;

    const int wrow_lo = q0 + wid * 16;
    int st = 0, st_n2 = 2;

    for (int t = 0; t < ntiles; t++) {
        if (t + 1 < ntiles) cp_wait<1>(); else cp_wait<0>();
        __syncthreads();                          // kv(t) visible; st_n2 free
        if (t + 2 < ntiles) kv_issue(t + 2, st_n2);

        const uint32_t kvb = sb + KV_OFF + st * KV_STG;
        st = (st == 2) ? 0 : st + 1;
        st_n2 = (st_n2 == 2) ? 0 : st_n2 + 1;

        if (t * 64 > wrow_lo + 15) continue;      // fully masked for warp

        // ---- S = Q @ K^T (term-major per kt) ----
        float acc_s[8][4];
        #pragma unroll
        for (int nt = 0; nt < 8; nt++)
            #pragma unroll
            for (int i = 0; i < 4; i++) acc_s[nt][i] = 0.0f;

        #pragma unroll
        for (int kt = 0; kt < 4; kt++) {
            uint32_t kh[4][4], kl[4][4];
            const uint32_t brow = (lane & 7) + ((lane & 16) >> 1);
            const uint32_t bcol = kt * 16 + ((lane >> 3) & 1) * 8;
            #pragma unroll
            for (int g = 0; g < 4; g++) {
                const uint32_t off = (g * 16 + brow) * AROWB + bcol * 2;
                ldsm_x4(kh[g], kvb + off);
                ldsm_x4(kl[g], kvb + 64 * AROWB + off);
            }
            #pragma unroll
            for (int nt = 0; nt < 8; nt++)
                mma16816(acc_s[nt], qhF[kt], &kh[nt >> 1][(nt & 1) * 2]);
            #pragma unroll
            for (int nt = 0; nt < 8; nt++)
                mma16816(acc_s[nt], qhF[kt], &kl[nt >> 1][(nt & 1) * 2]);
            #pragma unroll
            for (int nt = 0; nt < 8; nt++)
                mma16816(acc_s[nt], qlF[kt], &kh[nt >> 1][(nt & 1) * 2]);
        }

        // ---- causal mask ----
        const int r0 = q0 + wid * 16 + (lane >> 2);
        if (t * 64 + 63 > wrow_lo) {
            #pragma unroll
            for (int nt = 0; nt < 8; nt++)
                #pragma unroll
                for (int i = 0; i < 4; i++) {
                    const int row = r0 + (i >> 1) * 8;
                    const int col = t * 64 + nt * 8 + 2 * (lane & 3) + (i & 1);
                    if (col > row) acc_s[nt][i] = -1e30f;
                }
        }

        // ---- per-row tile max ----
        float tmax[2] = {-1e30f, -1e30f};
        #pragma unroll
        for (int nt = 0; nt < 8; nt++)
            #pragma unroll
            for (int i = 0; i < 4; i++)
                tmax[i >> 1] = fmaxf(tmax[i >> 1], acc_s[nt][i]);
        #pragma unroll
        for (int h = 0; h < 2; h++) {
            tmax[h] = fmaxf(tmax[h], __shfl_xor_sync(0xffffffffu, tmax[h], 1));
            tmax[h] = fmaxf(tmax[h], __shfl_xor_sync(0xffffffffu, tmax[h], 2));
        }

        // ---- vanishing-tile skip: every weight < e^-44 of running sum ----
        {
            float d = fmaxf(tmax[0] - m_s[0], tmax[1] - m_s[1]);
            d = fmaxf(d, __shfl_xor_sync(0xffffffffu, d, 4));
            d = fmaxf(d, __shfl_xor_sync(0xffffffffu, d, 8));
            d = fmaxf(d, __shfl_xor_sync(0xffffffffu, d, 16));
            if (d < -44.0f) continue;
        }

        // ---- online softmax ----
        float nm[2], corr[2];
        #pragma unroll
        for (int h = 0; h < 2; h++) {
            nm[h]   = fmaxf(m_s[h], tmax[h]);
            corr[h] = __expf(m_s[h] - nm[h]);
            m_s[h]  = nm[h];
        }
        float psum[2] = {0.0f, 0.0f};
        #pragma unroll
        for (int nt = 0; nt < 8; nt++)
            #pragma unroll
            for (int i = 0; i < 4; i++) {
                const float p = __expf(acc_s[nt][i] - nm[i >> 1]);
                acc_s[nt][i] = p;
                psum[i >> 1] += p;
            }
        #pragma unroll
        for (int h = 0; h < 2; h++) {
            psum[h] += __shfl_xor_sync(0xffffffffu, psum[h], 1);
            psum[h] += __shfl_xor_sync(0xffffffffu, psum[h], 2);
            l_s[h] = l_s[h] * corr[h] + psum[h];
        }
        #pragma unroll
        for (int nt = 0; nt < 8; nt++)
            #pragma unroll
            for (int i = 0; i < 4; i++) acc_o[nt][i] *= corr[i >> 1];

        // ---- pack P ----
        uint32_t ph[4][4], pl[4][4];
        #pragma unroll
        for (int kt = 0; kt < 4; kt++) {
            split2(acc_s[2 * kt][0],     acc_s[2 * kt][1],     ph[kt][0], pl[kt][0]);
            split2(acc_s[2 * kt][2],     acc_s[2 * kt][3],     ph[kt][1], pl[kt][1]);
            split2(acc_s[2 * kt + 1][0], acc_s[2 * kt + 1][1], ph[kt][2], pl[kt][2]);
            split2(acc_s[2 * kt + 1][2], acc_s[2 * kt + 1][3], ph[kt][3], pl[kt][3]);
        }

        // ---- O += P @ V (term-major per kt) ----
        #pragma unroll
        for (int kt = 0; kt < 4; kt++) {
            uint32_t vh[4][4], vl[4][4];
            const uint32_t vrow = kt * 16 + (lane & 15);
            const uint32_t vcol = (lane >> 4) * 8;
            #pragma unroll
            for (int g = 0; g < 4; g++) {
                const uint32_t off = vrow * AROWB + (g * 16 + vcol) * 2;
                ldsm_x4t(vh[g], kvb + 2 * 64 * AROWB + off);
                ldsm_x4t(vl[g], kvb + 3 * 64 * AROWB + off);
            }
            #pragma unroll
            for (int nt = 0; nt < 8; nt++)
                mma16816(acc_o[nt], ph[kt], &vh[nt >> 1][(nt & 1) * 2]);
            #pragma unroll
            for (int nt = 0; nt < 8; nt++)
                mma16816(acc_o[nt], pl[kt], &vh[nt >> 1][(nt & 1) * 2]);
            #pragma unroll
            for (int nt = 0; nt < 8; nt++)
                mma16816(acc_o[nt], ph[kt], &vl[nt >> 1][(nt & 1) * 2]);
        }
    }

    // ---- epilogue ----
    const float inv0 = 1.0f / l_s[0];
    const float inv1 = 1.0f / l_s[1];
    const int b  = bh >> 4;
    const int hh = bh & 15;
    const int r0 = q0 + wid * 16 + (lane >> 2);
    #pragma unroll
    for (int nt = 0; nt < 8; nt++) {
        const int col = hh * 64 + nt * 8 + 2 * (lane & 3);
        {
            const long idx = ((long)(b * S_LEN + r0)) * DMODEL + col;
            uint32_t hi, lo;
            split2(acc_o[nt][0] * inv0, acc_o[nt][1] * inv0, hi, lo);
            *(uint32_t*)(Ohi + idx) = hi;
            *(uint32_t*)(Olo + idx) = lo;
        }
        {
            const long idx = ((long)(b * S_LEN + r0 + 8)) * DMODEL + col;
            uint32_t hi, lo;
            split2(acc_o[nt][2] * inv1, acc_o[nt][3] * inv1, hi, lo);
            *(uint32_t*)(Ohi + idx) = hi;
            *(uint32_t*)(Olo + idx) = lo;
        }
    }
}

// ============================================================================
// conversion kernels (fused)
// ============================================================================
__global__ void __launch_bounds__(256)
conv_qkv(const float* __restrict__ q, const float* __restrict__ k,
         const float* __restrict__ v)
{
    const int z = blockIdx.y;
    const float* X = (z == 0) ? q : (z == 1) ? k : v;
    const int i = blockIdx.x * 256 + threadIdx.x;   // over float2
    const float2 x = ((const float2*)X)[i];
    uint32_t h, l;
    split2(x.x, x.y, h, l);
    ((uint32_t*)g_Ahi[z])[i] = h;
    ((uint32_t*)g_Alo[z])[i] = l;
}

__global__ void __launch_bounds__(256)
conv_w(const float* __restrict__ W0, const float* __restrict__ W1,
       const float* __restrict__ W2, const float* __restrict__ W3)
{
    __shared__ float t[32][33];
    const int z = blockIdx.z;
    const float* W = (z == 0) ? W0 : (z == 1) ? W1 : (z == 2) ? W2 : W3;
    const int tx = threadIdx.x, ty = threadIdx.y;     // (32, 8)
    const int n0 = blockIdx.x * 32, k0 = blockIdx.y * 32;
    #pragma unroll
    for (int r = 0; r < 4; r++) {
        const int k = ty + r * 8;
        t[k][tx] = W[(long)(k0 + k) * DMODEL + n0 + tx];
    }
    __syncthreads();
    #pragma unroll
    for (int r = 0; r < 4; r++) {
        const int nl = ty + r * 8;
        const float x = t[tx][nl];
        const __nv_bfloat16 h = __float2bfloat16(x);
        const long o = (long)(n0 + nl) * DMODEL + k0 + tx;
        g_Whi[z][o] = h;
        g_Wlo[z][o] = __float2bfloat16(x - __bfloat162float(h));
    }
}

// ============================================================================
extern "C" void kernel_launch(void* const* d_in, const int* in_sizes, int n_in,
                              void* d_out, int out_size)
{
    const float* q = (const float*)d_in[0];
    const float* k = (const float*)d_in[1];
    const float* v = (const float*)d_in[2];
    float* out = (float*)d_out;

    __nv_bfloat16 *whi, *wlo;
    __nv_bfloat16 *qhi, *qlo, *khi, *klo, *vhi, *vlo, *ohi, *olo;
    cudaGetSymbolAddress((void**)&whi, g_Whi);
    cudaGetSymbolAddress((void**)&wlo, g_Wlo);
    cudaGetSymbolAddress((void**)&qhi, g_Qhi);
    cudaGetSymbolAddress((void**)&qlo, g_Qlo);
    cudaGetSymbolAddress((void**)&khi, g_Khi);
    cudaGetSymbolAddress((void**)&klo, g_Klo);
    cudaGetSymbolAddress((void**)&vhi, g_Vhi);
    cudaGetSymbolAddress((void**)&vlo, g_Vlo);
    cudaGetSymbolAddress((void**)&ohi, g_Ohi);
    cudaGetSymbolAddress((void**)&olo, g_Olo);

    cudaFuncSetAttribute((const void*)gemm_qkv,
                         cudaFuncAttributeMaxDynamicSharedMemorySize, GSMEM);
    cudaFuncSetAttribute((const void*)gemm_out,
                         cudaFuncAttributeMaxDynamicSharedMemorySize, GSMEM);
    cudaFuncSetAttribute((const void*)attn_mma,
                         cudaFuncAttributeMaxDynamicSharedMemorySize, ASMEM);

    conv_w<<<dim3(32, 32, 4), dim3(32, 8)>>>(
        (const float*)d_in[3], (const float*)d_in[4],
        (const float*)d_in[5], (const float*)d_in[6]);

    conv_qkv<<<dim3(AELEMS / 2 / 256, 3), 256>>>(q, k, v);

    gemm_qkv<<<dim3(8, 64, 3), 256, GSMEM>>>(qhi, qlo, khi, klo, vhi, vlo);

    attn_mma<<<dim3(S_LEN / 128, BHCNT), 256, ASMEM>>>(qhi, qlo, khi, klo,
                                                       vhi, vlo, ohi, olo);

    gemm_out<<<dim3(8, 64), 256, GSMEM>>>(ohi, olo,
        whi + 3 * (long)WELEMS, wlo + 3 * (long)WELEMS, out);
}

// round 7
// speedup vs baseline: 3.4693x; 1.0375x over previous
#include <cuda_runtime.h>
#include <cuda_bf16.h>
#include <cstdint>

#define S_LEN   2048
#define DMODEL  1024
#define NHEADS  16
#define HDIM    64
#define BATCH   4
#define BHCNT   (BATCH * NHEADS)                   // 64
#define MROWS   (BATCH * S_LEN)                    // 8192
#define HS_ELEMS (BATCH * NHEADS * S_LEN * HDIM)   // 8388608
#define AELEMS  (MROWS * DMODEL)                   // 8388608
#define WELEMS  (DMODEL * DMODEL)                  // 1048576

// ---- scratch (all bf16 hi/lo pairs) ----
__device__ __nv_bfloat16 g_Ahi[3][AELEMS];
__device__ __nv_bfloat16 g_Alo[3][AELEMS];
__device__ __nv_bfloat16 g_Whi[4][WELEMS];   // transposed [N][K]
__device__ __nv_bfloat16 g_Wlo[4][WELEMS];
__device__ __nv_bfloat16 g_Qhi[HS_ELEMS], g_Qlo[HS_ELEMS];   // head-split, pre-scaled 1/8
__device__ __nv_bfloat16 g_Khi[HS_ELEMS], g_Klo[HS_ELEMS];
__device__ __nv_bfloat16 g_Vhi[HS_ELEMS], g_Vlo[HS_ELEMS];
__device__ __nv_bfloat16 g_Ohi[AELEMS],  g_Olo[AELEMS];      // row-major [8192][1024]

// ============================================================================
// helpers (baseline PTX only)
// ============================================================================
__device__ __forceinline__ uint32_t smem_u32(const void* p) {
    uint32_t a;
    asm("{ .reg .u64 t; cvta.to.shared.u64 t, %1; cvt.u32.u64 %0, t; }"
        : "=r"(a) : "l"(p));
    return a;
}
__device__ __forceinline__ void cp_async16(uint32_t dst, const void* src) {
    asm volatile("cp.async.cg.shared.global [%0], [%1], 16;"
                 :: "r"(dst), "l"(src));
}
__device__ __forceinline__ void cp_commit() {
    asm volatile("cp.async.commit_group;");
}
template <int N>
__device__ __forceinline__ void cp_wait() {
    asm volatile("cp.async.wait_group %0;" :: "n"(N));
}
__device__ __forceinline__ void ldsm_x4(uint32_t* r, uint32_t addr) {
    asm volatile("ldmatrix.sync.aligned.m8n8.x4.shared.b16 {%0,%1,%2,%3}, [%4];"
                 : "=r"(r[0]), "=r"(r[1]), "=r"(r[2]), "=r"(r[3]) : "r"(addr));
}
__device__ __forceinline__ void ldsm_x4t(uint32_t* r, uint32_t addr) {
    asm volatile("ldmatrix.sync.aligned.m8n8.x4.trans.shared.b16 {%0,%1,%2,%3}, [%4];"
                 : "=r"(r[0]), "=r"(r[1]), "=r"(r[2]), "=r"(r[3]) : "r"(addr));
}
__device__ __forceinline__ void mma16816(float* d, const uint32_t* a,
                                         const uint32_t* b) {
    asm volatile("mma.sync.aligned.m16n8k16.row.col.f32.bf16.bf16.f32 "
                 "{%0,%1,%2,%3}, {%4,%5,%6,%7}, {%8,%9}, {%0,%1,%2,%3};"
                 : "+f"(d[0]), "+f"(d[1]), "+f"(d[2]), "+f"(d[3])
                 : "r"(a[0]), "r"(a[1]), "r"(a[2]), "r"(a[3]),
                   "r"(b[0]), "r"(b[1]));
}
__device__ __forceinline__ void split2(float a, float b,
                                       uint32_t& hi, uint32_t& lo) {
    __nv_bfloat16 ha = __float2bfloat16(a), hb = __float2bfloat16(b);
    __nv_bfloat16 la = __float2bfloat16(a - __bfloat162float(ha));
    __nv_bfloat16 lb = __float2bfloat16(b - __bfloat162float(hb));
    hi = (uint32_t)*(uint16_t*)&ha | ((uint32_t)*(uint16_t*)&hb << 16);
    lo = (uint32_t)*(uint16_t*)&la | ((uint32_t)*(uint16_t*)&lb << 16);
}

// ============================================================================
// GEMM mainloop: tile 64(M)x128(N), BK=32, 4 warps (2Mx2N), split-bf16 3-term.
// 3-stage cp.async pipeline, ONE __syncthreads per K-chunk. 128 threads.
// ============================================================================
#define ROWB       80
#define GA_BYTES   (64 * ROWB)               // 5120  (one A array)
#define GB_BYTES   (128 * ROWB)              // 10240 (one B array)
#define STG_BYTES  (2 * GA_BYTES + 2 * GB_BYTES)  // 30720
#define GSMEM      (3 * STG_BYTES)           // 92160
// stage offsets: AHI 0, ALO 5120, BHI 10240, BLO 20480

__device__ __forceinline__ void gemm_core(
    const __nv_bfloat16* __restrict__ Ahi, const __nv_bfloat16* __restrict__ Alo,
    const __nv_bfloat16* __restrict__ Bhi, const __nv_bfloat16* __restrict__ Blo,
    uint32_t sb, int tid, int bc, int br, float acc[2][8][4])
{
    const int lane   = tid & 31;
    const int wid    = tid >> 5;          // 0..3
    const int warp_m = wid >> 1;
    const int warp_n = wid & 1;

    auto issue = [&](int kc, int stage) {
        #pragma unroll
        for (int t = 0; t < 12; t++) {
            const int c = tid + t * 128;   // 0..1535
            uint32_t dst;
            const __nv_bfloat16* g;
            if (c < 512) {
                const int arr = c >> 8, rem = c & 255;
                const int row = rem >> 2, seg = rem & 3;
                g = (arr ? Alo : Ahi) + (long)(br * 64 + row) * DMODEL
                  + kc * 32 + seg * 8;
                dst = sb + stage * STG_BYTES + arr * GA_BYTES
                    + row * ROWB + seg * 16;
            } else {
                const int cb = c - 512;
                const int arr = cb >> 9, rem = cb & 511;
                const int row = rem >> 2, seg = rem & 3;
                g = (arr ? Blo : Bhi) + (long)(bc * 128 + row) * DMODEL
                  + kc * 32 + seg * 8;
                dst = sb + stage * STG_BYTES + 2 * GA_BYTES + arr * GB_BYTES
                    + row * ROWB + seg * 16;
            }
            cp_async16(dst, g);
        }
        cp_commit();
    };

    issue(0, 0);
    issue(1, 1);

    const int NKC = DMODEL / 32;         // 32
    int st = 0, st_n2 = 2;
    for (int kc = 0; kc < NKC; kc++) {
        if (kc + 1 < NKC) cp_wait<1>(); else cp_wait<0>();
        __syncthreads();
        if (kc + 2 < NKC) issue(kc + 2, st_n2);

        const uint32_t base = sb + st * STG_BYTES;

        #pragma unroll
        for (int kk = 0; kk < 2; kk++) {
            uint32_t ahi[2][4], alo[2][4];
            {
                const uint32_t arow = warp_m * 32 + (lane & 15);
                const uint32_t acol = kk * 16 + (lane >> 4) * 8;
                const uint32_t off  = arow * ROWB + acol * 2;
                ldsm_x4(ahi[0], base + off);
                ldsm_x4(ahi[1], base + off + 16 * ROWB);
                ldsm_x4(alo[0], base + GA_BYTES + off);
                ldsm_x4(alo[1], base + GA_BYTES + off + 16 * ROWB);
            }
            uint32_t bhi[4][4], blo[4][4];
            {
                const uint32_t brow = warp_n * 64 + (lane & 7) + ((lane & 16) >> 1);
                const uint32_t bcol = kk * 16 + ((lane >> 3) & 1) * 8;
                const uint32_t off  = brow * ROWB + bcol * 2;
                #pragma unroll
                for (int q = 0; q < 4; q++) {
                    ldsm_x4(bhi[q], base + 2 * GA_BYTES + off + q * 16 * ROWB);
                    ldsm_x4(blo[q], base + 2 * GA_BYTES + GB_BYTES + off
                                    + q * 16 * ROWB);
                }
            }
            #pragma unroll
            for (int mt = 0; mt < 2; mt++)
                #pragma unroll
                for (int nt = 0; nt < 8; nt++)
                    mma16816(acc[mt][nt], ahi[mt], &bhi[nt >> 1][(nt & 1) * 2]);
            #pragma unroll
            for (int mt = 0; mt < 2; mt++)
                #pragma unroll
                for (int nt = 0; nt < 8; nt++)
                    mma16816(acc[mt][nt], ahi[mt], &blo[nt >> 1][(nt & 1) * 2]);
            #pragma unroll
            for (int mt = 0; mt < 2; mt++)
                #pragma unroll
                for (int nt = 0; nt < 8; nt++)
                    mma16816(acc[mt][nt], alo[mt], &bhi[nt >> 1][(nt & 1) * 2]);
        }

        st = (st == 2) ? 0 : st + 1;
        st_n2 = (st_n2 == 2) ? 0 : st_n2 + 1;
    }
}

// ============================================================================
// Batched QKV projection GEMM: grid (8, 128, 3), 128 threads.
// ============================================================================
__global__ void __launch_bounds__(128, 2)
gemm_qkv(__nv_bfloat16* __restrict__ Qhi, __nv_bfloat16* __restrict__ Qlo,
         __nv_bfloat16* __restrict__ Khi, __nv_bfloat16* __restrict__ Klo,
         __nv_bfloat16* __restrict__ Vhi, __nv_bfloat16* __restrict__ Vlo)
{
    extern __shared__ char smem[];
    const uint32_t sb = smem_u32(smem);
    const int tid = threadIdx.x;
    const int bc = blockIdx.x, br = blockIdx.y, z = blockIdx.z;

    __nv_bfloat16 *Chi, *Clo;
    float scale;
    if (z == 0)      { Chi = Qhi; Clo = Qlo; scale = 0.125f; }
    else if (z == 1) { Chi = Khi; Clo = Klo; scale = 1.0f; }
    else             { Chi = Vhi; Clo = Vlo; scale = 1.0f; }

    float acc[2][8][4];
    #pragma unroll
    for (int mt = 0; mt < 2; mt++)
        #pragma unroll
        for (int nt = 0; nt < 8; nt++)
            #pragma unroll
            for (int i = 0; i < 4; i++) acc[mt][nt][i] = 0.0f;

    gemm_core(g_Ahi[z], g_Alo[z], g_Whi[z], g_Wlo[z], sb, tid, bc, br, acc);

    const int lane = tid & 31, wid = tid >> 5;
    const int warp_m = wid >> 1, warp_n = wid & 1;
    #pragma unroll
    for (int mt = 0; mt < 2; mt++) {
        #pragma unroll
        for (int nt = 0; nt < 8; nt++) {
            const int row0 = br * 64 + warp_m * 32 + mt * 16 + (lane >> 2);
            const int col  = bc * 128 + warp_n * 64 + nt * 8 + (lane & 3) * 2;
            const int h = col >> 6, dd = col & 63;
            #pragma unroll
            for (int half = 0; half < 2; half++) {
                const int r = row0 + half * 8;
                const int b = r >> 11, s = r & 2047;
                const long off = ((((long)b * NHEADS + h) * S_LEN + s) * HDIM) + dd;
                uint32_t hi, lo;
                split2(acc[mt][nt][half * 2] * scale,
                       acc[mt][nt][half * 2 + 1] * scale, hi, lo);
                *(uint32_t*)(Chi + off) = hi;
                *(uint32_t*)(Clo + off) = lo;
            }
        }
    }
}

// ============================================================================
// Output projection GEMM: fp32 row-major result. grid (8, 128), 128 threads.
// ============================================================================
__global__ void __launch_bounds__(128, 2)
gemm_out(const __nv_bfloat16* __restrict__ Ahi, const __nv_bfloat16* __restrict__ Alo,
         const __nv_bfloat16* __restrict__ Bhi, const __nv_bfloat16* __restrict__ Blo,
         float* __restrict__ Cf)
{
    extern __shared__ char smem[];
    const uint32_t sb = smem_u32(smem);
    const int tid = threadIdx.x;
    const int bc = blockIdx.x, br = blockIdx.y;

    float acc[2][8][4];
    #pragma unroll
    for (int mt = 0; mt < 2; mt++)
        #pragma unroll
        for (int nt = 0; nt < 8; nt++)
            #pragma unroll
            for (int i = 0; i < 4; i++) acc[mt][nt][i] = 0.0f;

    gemm_core(Ahi, Alo, Bhi, Blo, sb, tid, bc, br, acc);

    const int lane = tid & 31, wid = tid >> 5;
    const int warp_m = wid >> 1, warp_n = wid & 1;
    #pragma unroll
    for (int mt = 0; mt < 2; mt++) {
        #pragma unroll
        for (int nt = 0; nt < 8; nt++) {
            const int row0 = br * 64 + warp_m * 32 + mt * 16 + (lane >> 2);
            const int col  = bc * 128 + warp_n * 64 + nt * 8 + (lane & 3) * 2;
            float2 v01; v01.x = acc[mt][nt][0]; v01.y = acc[mt][nt][1];
            float2 v23; v23.x = acc[mt][nt][2]; v23.y = acc[mt][nt][3];
            *(float2*)&Cf[(long)row0 * DMODEL + col] = v01;
            *(float2*)&Cf[(long)(row0 + 8) * DMODEL + col] = v23;
        }
    }
}

// ============================================================================
// Tensor-core causal flash attention. 128 threads (4 warps x m16 = 64 q-rows).
// 3-stage KV ring; Q staged through ring slot 2 then overwritten.
// grid (32, 64); q-blocks issued longest-first.
// ============================================================================
#define AROWB    144
#define KVARR    (64 * AROWB)            // 9216  one array (64 rows)
#define KV_STG   (4 * KVARR)             // 36864 per stage
#define ASMEM    (3 * KV_STG)            // 110592
// Q staged at ring slot 2: Qhi at 2*KV_STG, Qlo at 2*KV_STG + KVARR

__global__ void __launch_bounds__(128, 2)
attn_mma(const __nv_bfloat16* __restrict__ Qhi, const __nv_bfloat16* __restrict__ Qlo,
         const __nv_bfloat16* __restrict__ Khi, const __nv_bfloat16* __restrict__ Klo,
         const __nv_bfloat16* __restrict__ Vhi, const __nv_bfloat16* __restrict__ Vlo,
         __nv_bfloat16* __restrict__ Ohi, __nv_bfloat16* __restrict__ Olo)
{
    extern __shared__ char smem[];
    const uint32_t sb = smem_u32(smem);
    const int tid = threadIdx.x, wid = tid >> 5, lane = tid & 31;
    const int qblk = (int)gridDim.x - 1 - (int)blockIdx.x;   // longest first
    const int q0 = qblk * 64;
    const int bh = blockIdx.y;
    const long base = (long)bh * S_LEN * HDIM;

    // ---- Q load into ring slot 2 (own group) ----
    {
        #pragma unroll
        for (int t = 0; t < 8; t++) {
            const int c = tid + t * 128;            // 0..1023
            const int arr = c >> 9, rem = c & 511;
            const int row = rem >> 3, seg = rem & 7;
            const __nv_bfloat16* src = (arr ? Qlo : Qhi)
                                     + base + (long)(q0 + row) * HDIM + seg * 8;
            cp_async16(sb + 2 * KV_STG + arr * KVARR + row * AROWB + seg * 16, src);
        }
        cp_commit();
    }

    const int ntiles = qblk + 1;

    auto kv_issue = [&](int t, int stage) {
        #pragma unroll
        for (int i = 0; i < 16; i++) {
            const int c = tid + i * 128;            // 0..2047
            const int arr = c >> 9, rem = c & 511;
            const int row = rem >> 3, seg = rem & 7;
            const __nv_bfloat16* p;
            if (arr == 0)      p = Khi;
            else if (arr == 1) p = Klo;
            else if (arr == 2) p = Vhi;
            else               p = Vlo;
            cp_async16(sb + stage * KV_STG + arr * KVARR + row * AROWB + seg * 16,
                       p + base + (long)(t * 64 + row) * HDIM + seg * 8);
        }
        cp_commit();
    };

    kv_issue(0, 0);
    kv_issue(1, 1);     // tile 1 always within K/V allocation (<= 2048 rows)
    cp_wait<2>();       // Q resident
    __syncthreads();

    // ---- persistent Q fragments (from ring slot 2) ----
    uint32_t qhF[4][4], qlF[4][4];
    {
        const uint32_t arow = wid * 16 + (lane & 15);
        #pragma unroll
        for (int kt = 0; kt < 4; kt++) {
            const uint32_t off = arow * AROWB + (kt * 16 + (lane >> 4) * 8) * 2;
            ldsm_x4(qhF[kt], sb + 2 * KV_STG + off);
            ldsm_x4(qlF[kt], sb + 2 * KV_STG + KVARR + off);
        }
    }

    float m_s[2] = {-1e30f, -1e30f};
    float l_s[2] = {0.0f, 0.0f};
    float acc_o[8][4];
    #pragma unroll
    for (int nt = 0; nt < 8; nt++)
        #pragma unroll
        for (int i = 0; i < 4; i++) acc_o[nt][i] = 0.0f;

    const int wrow_lo = q0 + wid * 16;
    int st = 0, st_n2 = 2;

    for (int t = 0; t < ntiles; t++) {
        cp_wait<1>();                 // tile t resident (see group accounting)
        __syncthreads();              // Q-frag/ring readers of st_n2 done
        if (t + 2 < ntiles) kv_issue(t + 2, st_n2);

        const uint32_t kvb = sb + st * KV_STG;
        st = (st == 2) ? 0 : st + 1;
        st_n2 = (st_n2 == 2) ? 0 : st_n2 + 1;

        if (t * 64 > wrow_lo + 15) continue;      // fully masked for warp

        // ---- S = Q @ K^T (term-major per kt) ----
        float acc_s[8][4];
        #pragma unroll
        for (int nt = 0; nt < 8; nt++)
            #pragma unroll
            for (int i = 0; i < 4; i++) acc_s[nt][i] = 0.0f;

        #pragma unroll
        for (int kt = 0; kt < 4; kt++) {
            uint32_t kh[4][4], kl[4][4];
            const uint32_t brow = (lane & 7) + ((lane & 16) >> 1);
            const uint32_t bcol = kt * 16 + ((lane >> 3) & 1) * 8;
            #pragma unroll
            for (int g = 0; g < 4; g++) {
                const uint32_t off = (g * 16 + brow) * AROWB + bcol * 2;
                ldsm_x4(kh[g], kvb + off);
                ldsm_x4(kl[g], kvb + KVARR + off);
            }
            #pragma unroll
            for (int nt = 0; nt < 8; nt++)
                mma16816(acc_s[nt], qhF[kt], &kh[nt >> 1][(nt & 1) * 2]);
            #pragma unroll
            for (int nt = 0; nt < 8; nt++)
                mma16816(acc_s[nt], qhF[kt], &kl[nt >> 1][(nt & 1) * 2]);
            #pragma unroll
            for (int nt = 0; nt < 8; nt++)
                mma16816(acc_s[nt], qlF[kt], &kh[nt >> 1][(nt & 1) * 2]);
        }

        // ---- causal mask ----
        const int r0 = q0 + wid * 16 + (lane >> 2);
        if (t * 64 + 63 > wrow_lo) {
            #pragma unroll
            for (int nt = 0; nt < 8; nt++)
                #pragma unroll
                for (int i = 0; i < 4; i++) {
                    const int row = r0 + (i >> 1) * 8;
                    const int col = t * 64 + nt * 8 + 2 * (lane & 3) + (i & 1);
                    if (col > row) acc_s[nt][i] = -1e30f;
                }
        }

        // ---- per-row tile max ----
        float tmax[2] = {-1e30f, -1e30f};
        #pragma unroll
        for (int nt = 0; nt < 8; nt++)
            #pragma unroll
            for (int i = 0; i < 4; i++)
                tmax[i >> 1] = fmaxf(tmax[i >> 1], acc_s[nt][i]);
        #pragma unroll
        for (int h = 0; h < 2; h++) {
            tmax[h] = fmaxf(tmax[h], __shfl_xor_sync(0xffffffffu, tmax[h], 1));
            tmax[h] = fmaxf(tmax[h], __shfl_xor_sync(0xffffffffu, tmax[h], 2));
        }

        // ---- vanishing-tile skip ----
        {
            float d = fmaxf(tmax[0] - m_s[0], tmax[1] - m_s[1]);
            d = fmaxf(d, __shfl_xor_sync(0xffffffffu, d, 4));
            d = fmaxf(d, __shfl_xor_sync(0xffffffffu, d, 8));
            d = fmaxf(d, __shfl_xor_sync(0xffffffffu, d, 16));
            if (d < -44.0f) continue;
        }

        // ---- online softmax ----
        float nm[2], corr[2];
        #pragma unroll
        for (int h = 0; h < 2; h++) {
            nm[h]   = fmaxf(m_s[h], tmax[h]);
            corr[h] = __expf(m_s[h] - nm[h]);
            m_s[h]  = nm[h];
        }
        float psum[2] = {0.0f, 0.0f};
        #pragma unroll
        for (int nt = 0; nt < 8; nt++)
            #pragma unroll
            for (int i = 0; i < 4; i++) {
                const float p = __expf(acc_s[nt][i] - nm[i >> 1]);
                acc_s[nt][i] = p;
                psum[i >> 1] += p;
            }
        #pragma unroll
        for (int h = 0; h < 2; h++) {
            psum[h] += __shfl_xor_sync(0xffffffffu, psum[h], 1);
            psum[h] += __shfl_xor_sync(0xffffffffu, psum[h], 2);
            l_s[h] = l_s[h] * corr[h] + psum[h];
        }
        #pragma unroll
        for (int nt = 0; nt < 8; nt++)
            #pragma unroll
            for (int i = 0; i < 4; i++) acc_o[nt][i] *= corr[i >> 1];

        // ---- pack P ----
        uint32_t ph[4][4], pl[4][4];
        #pragma unroll
        for (int kt = 0; kt < 4; kt++) {
            split2(acc_s[2 * kt][0],     acc_s[2 * kt][1],     ph[kt][0], pl[kt][0]);
            split2(acc_s[2 * kt][2],     acc_s[2 * kt][3],     ph[kt][1], pl[kt][1]);
            split2(acc_s[2 * kt + 1][0], acc_s[2 * kt + 1][1], ph[kt][2], pl[kt][2]);
            split2(acc_s[2 * kt + 1][2], acc_s[2 * kt + 1][3], ph[kt][3], pl[kt][3]);
        }

        // ---- O += P @ V (term-major per kt) ----
        #pragma unroll
        for (int kt = 0; kt < 4; kt++) {
            uint32_t vh[4][4], vl[4][4];
            const uint32_t vrow = kt * 16 + (lane & 15);
            const uint32_t vcol = (lane >> 4) * 8;
            #pragma unroll
            for (int g = 0; g < 4; g++) {
                const uint32_t off = vrow * AROWB + (g * 16 + vcol) * 2;
                ldsm_x4t(vh[g], kvb + 2 * KVARR + off);
                ldsm_x4t(vl[g], kvb + 3 * KVARR + off);
            }
            #pragma unroll
            for (int nt = 0; nt < 8; nt++)
                mma16816(acc_o[nt], ph[kt], &vh[nt >> 1][(nt & 1) * 2]);
            #pragma unroll
            for (int nt = 0; nt < 8; nt++)
                mma16816(acc_o[nt], pl[kt], &vh[nt >> 1][(nt & 1) * 2]);
            #pragma unroll
            for (int nt = 0; nt < 8; nt++)
                mma16816(acc_o[nt], ph[kt], &vl[nt >> 1][(nt & 1) * 2]);
        }
    }

    // ---- epilogue ----
    const float inv0 = 1.0f / l_s[0];
    const float inv1 = 1.0f / l_s[1];
    const int b  = bh >> 4;
    const int hh = bh & 15;
    const int r0 = q0 + wid * 16 + (lane >> 2);
    #pragma unroll
    for (int nt = 0; nt < 8; nt++) {
        const int col = hh * 64 + nt * 8 + 2 * (lane & 3);
        {
            const long idx = ((long)(b * S_LEN + r0)) * DMODEL + col;
            uint32_t hi, lo;
            split2(acc_o[nt][0] * inv0, acc_o[nt][1] * inv0, hi, lo);
            *(uint32_t*)(Ohi + idx) = hi;
            *(uint32_t*)(Olo + idx) = lo;
        }
        {
            const long idx = ((long)(b * S_LEN + r0 + 8)) * DMODEL + col;
            uint32_t hi, lo;
            split2(acc_o[nt][2] * inv1, acc_o[nt][3] * inv1, hi, lo);
            *(uint32_t*)(Ohi + idx) = hi;
            *(uint32_t*)(Olo + idx) = lo;
        }
    }
}

// ============================================================================
// conversion kernels (fused)
// ============================================================================
__global__ void __launch_bounds__(256)
conv_qkv(const float* __restrict__ q, const float* __restrict__ k,
         const float* __restrict__ v)
{
    const int z = blockIdx.y;
    const float* X = (z == 0) ? q : (z == 1) ? k : v;
    const int i = blockIdx.x * 256 + threadIdx.x;   // over float2
    const float2 x = ((const float2*)X)[i];
    uint32_t h, l;
    split2(x.x, x.y, h, l);
    ((uint32_t*)g_Ahi[z])[i] = h;
    ((uint32_t*)g_Alo[z])[i] = l;
}

__global__ void __launch_bounds__(256)
conv_w(const float* __restrict__ W0, const float* __restrict__ W1,
       const float* __restrict__ W2, const float* __restrict__ W3)
{
    __shared__ float t[32][33];
    const int z = blockIdx.z;
    const float* W = (z == 0) ? W0 : (z == 1) ? W1 : (z == 2) ? W2 : W3;
    const int tx = threadIdx.x, ty = threadIdx.y;     // (32, 8)
    const int n0 = blockIdx.x * 32, k0 = blockIdx.y * 32;
    #pragma unroll
    for (int r = 0; r < 4; r++) {
        const int k = ty + r * 8;
        t[k][tx] = W[(long)(k0 + k) * DMODEL + n0 + tx];
    }
    __syncthreads();
    #pragma unroll
    for (int r = 0; r < 4; r++) {
        const int nl = ty + r * 8;
        const float x = t[tx][nl];
        const __nv_bfloat16 h = __float2bfloat16(x);
        const long o = (long)(n0 + nl) * DMODEL + k0 + tx;
        g_Whi[z][o] = h;
        g_Wlo[z][o] = __float2bfloat16(x - __bfloat162float(h));
    }
}

// ============================================================================
extern "C" void kernel_launch(void* const* d_in, const int* in_sizes, int n_in,
                              void* d_out, int out_size)
{
    const float* q = (const float*)d_in[0];
    const float* k = (const float*)d_in[1];
    const float* v = (const float*)d_in[2];
    float* out = (float*)d_out;

    __nv_bfloat16 *whi, *wlo;
    __nv_bfloat16 *qhi, *qlo, *khi, *klo, *vhi, *vlo, *ohi, *olo;
    cudaGetSymbolAddress((void**)&whi, g_Whi);
    cudaGetSymbolAddress((void**)&wlo, g_Wlo);
    cudaGetSymbolAddress((void**)&qhi, g_Qhi);
    cudaGetSymbolAddress((void**)&qlo, g_Qlo);
    cudaGetSymbolAddress((void**)&khi, g_Khi);
    cudaGetSymbolAddress((void**)&klo, g_Klo);
    cudaGetSymbolAddress((void**)&vhi, g_Vhi);
    cudaGetSymbolAddress((void**)&vlo, g_Vlo);
    cudaGetSymbolAddress((void**)&ohi, g_Ohi);
    cudaGetSymbolAddress((void**)&olo, g_Olo);

    cudaFuncSetAttribute((const void*)gemm_qkv,
                         cudaFuncAttributeMaxDynamicSharedMemorySize, GSMEM);
    cudaFuncSetAttribute((const void*)gemm_out,
                         cudaFuncAttributeMaxDynamicSharedMemorySize, GSMEM);
    cudaFuncSetAttribute((const void*)attn_mma,
                         cudaFuncAttributeMaxDynamicSharedMemorySize, ASMEM);

    conv_w<<<dim3(32, 32, 4), dim3(32, 8)>>>(
        (const float*)d_in[3], (const float*)d_in[4],
        (const float*)d_in[5], (const float*)d_in[6]);

    conv_qkv<<<dim3(AELEMS / 2 / 256, 3), 256>>>(q, k, v);

    gemm_qkv<<<dim3(8, 128, 3), 128, GSMEM>>>(qhi, qlo, khi, klo, vhi, vlo);

    attn_mma<<<dim3(S_LEN / 64, BHCNT), 128, ASMEM>>>(qhi, qlo, khi, klo,
                                                      vhi, vlo, ohi, olo);

    gemm_out<<<dim3(8, 128), 128, GSMEM>>>(ohi, olo,
        whi + 3 * (long)WELEMS, wlo + 3 * (long)WELEMS, out);
}

// round 8
// speedup vs baseline: 3.8557x; 1.1114x over previous
#include <cuda_runtime.h>
#include <cuda_bf16.h>
#include <cstdint>

#define S_LEN   2048
#define DMODEL  1024
#define NHEADS  16
#define HDIM    64
#define BATCH   4
#define BHCNT   (BATCH * NHEADS)                   // 64
#define MROWS   (BATCH * S_LEN)                    // 8192
#define HS_ELEMS (BATCH * NHEADS * S_LEN * HDIM)   // 8388608
#define AELEMS  (MROWS * DMODEL)                   // 8388608
#define WELEMS  (DMODEL * DMODEL)                  // 1048576

// ---- scratch (all bf16 hi/lo pairs) ----
__device__ __nv_bfloat16 g_Ahi[3][AELEMS];
__device__ __nv_bfloat16 g_Alo[3][AELEMS];
__device__ __nv_bfloat16 g_Whi[4][WELEMS];   // transposed [N][K]
__device__ __nv_bfloat16 g_Wlo[4][WELEMS];
__device__ __nv_bfloat16 g_Qhi[HS_ELEMS], g_Qlo[HS_ELEMS];   // head-split, pre-scaled 1/8
__device__ __nv_bfloat16 g_Khi[HS_ELEMS], g_Klo[HS_ELEMS];
__device__ __nv_bfloat16 g_Vhi[HS_ELEMS], g_Vlo[HS_ELEMS];
__device__ __nv_bfloat16 g_Ohi[AELEMS],  g_Olo[AELEMS];      // row-major [8192][1024]

// ============================================================================
// helpers (baseline PTX only)
// ============================================================================
__device__ __forceinline__ uint32_t smem_u32(const void* p) {
    uint32_t a;
    asm("{ .reg .u64 t; cvta.to.shared.u64 t, %1; cvt.u32.u64 %0, t; }"
        : "=r"(a) : "l"(p));
    return a;
}
__device__ __forceinline__ void cp_async16(uint32_t dst, const void* src) {
    asm volatile("cp.async.cg.shared.global [%0], [%1], 16;"
                 :: "r"(dst), "l"(src));
}
__device__ __forceinline__ void cp_commit() {
    asm volatile("cp.async.commit_group;");
}
template <int N>
__device__ __forceinline__ void cp_wait() {
    asm volatile("cp.async.wait_group %0;" :: "n"(N));
}
__device__ __forceinline__ void ldsm_x4(uint32_t* r, uint32_t addr) {
    asm volatile("ldmatrix.sync.aligned.m8n8.x4.shared.b16 {%0,%1,%2,%3}, [%4];"
                 : "=r"(r[0]), "=r"(r[1]), "=r"(r[2]), "=r"(r[3]) : "r"(addr));
}
__device__ __forceinline__ void ldsm_x4t(uint32_t* r, uint32_t addr) {
    asm volatile("ldmatrix.sync.aligned.m8n8.x4.trans.shared.b16 {%0,%1,%2,%3}, [%4];"
                 : "=r"(r[0]), "=r"(r[1]), "=r"(r[2]), "=r"(r[3]) : "r"(addr));
}
__device__ __forceinline__ void mma16816(float* d, const uint32_t* a,
                                         const uint32_t* b) {
    asm volatile("mma.sync.aligned.m16n8k16.row.col.f32.bf16.bf16.f32 "
                 "{%0,%1,%2,%3}, {%4,%5,%6,%7}, {%8,%9}, {%0,%1,%2,%3};"
                 : "+f"(d[0]), "+f"(d[1]), "+f"(d[2]), "+f"(d[3])
                 : "r"(a[0]), "r"(a[1]), "r"(a[2]), "r"(a[3]),
                   "r"(b[0]), "r"(b[1]));
}
__device__ __forceinline__ void split2(float a, float b,
                                       uint32_t& hi, uint32_t& lo) {
    __nv_bfloat16 ha = __float2bfloat16(a), hb = __float2bfloat16(b);
    __nv_bfloat16 la = __float2bfloat16(a - __bfloat162float(ha));
    __nv_bfloat16 lb = __float2bfloat16(b - __bfloat162float(hb));
    hi = (uint32_t)*(uint16_t*)&ha | ((uint32_t)*(uint16_t*)&hb << 16);
    lo = (uint32_t)*(uint16_t*)&la | ((uint32_t)*(uint16_t*)&lb << 16);
}

// ============================================================================
// GEMM mainloop: tile 64(M)x128(N), BK=32, 4 warps (2Mx2N), split-bf16 3-term.
// 2-stage cp.async pipeline, one __syncthreads per K-chunk. 128 threads.
// ============================================================================
#define ROWB       80
#define GA_BYTES   (64 * ROWB)               // 5120  (one A array)
#define GB_BYTES   (128 * ROWB)              // 10240 (one B array)
#define STG_BYTES  (2 * GA_BYTES + 2 * GB_BYTES)  // 30720
#define GSMEM      (2 * STG_BYTES)           // 61440

__device__ __forceinline__ void gemm_core(
    const __nv_bfloat16* __restrict__ Ahi, const __nv_bfloat16* __restrict__ Alo,
    const __nv_bfloat16* __restrict__ Bhi, const __nv_bfloat16* __restrict__ Blo,
    uint32_t sb, int tid, int bc, int br, float acc[2][8][4])
{
    const int lane   = tid & 31;
    const int wid    = tid >> 5;          // 0..3
    const int warp_m = wid >> 1;
    const int warp_n = wid & 1;

    auto issue = [&](int kc, int stage) {
        #pragma unroll
        for (int t = 0; t < 12; t++) {
            const int c = tid + t * 128;   // 0..1535
            uint32_t dst;
            const __nv_bfloat16* g;
            if (c < 512) {
                const int arr = c >> 8, rem = c & 255;
                const int row = rem >> 2, seg = rem & 3;
                g = (arr ? Alo : Ahi) + (long)(br * 64 + row) * DMODEL
                  + kc * 32 + seg * 8;
                dst = sb + stage * STG_BYTES + arr * GA_BYTES
                    + row * ROWB + seg * 16;
            } else {
                const int cb = c - 512;
                const int arr = cb >> 9, rem = cb & 511;
                const int row = rem >> 2, seg = rem & 3;
                g = (arr ? Blo : Bhi) + (long)(bc * 128 + row) * DMODEL
                  + kc * 32 + seg * 8;
                dst = sb + stage * STG_BYTES + 2 * GA_BYTES + arr * GB_BYTES
                    + row * ROWB + seg * 16;
            }
            cp_async16(dst, g);
        }
        cp_commit();
    };

    issue(0, 0);

    const int NKC = DMODEL / 32;         // 32
    for (int kc = 0; kc < NKC; kc++) {
        cp_wait<0>();                    // stage kc resident
        __syncthreads();                 // visible; other stage free
        if (kc + 1 < NKC) issue(kc + 1, (kc + 1) & 1);

        const uint32_t base = sb + (kc & 1) * STG_BYTES;

        #pragma unroll
        for (int kk = 0; kk < 2; kk++) {
            uint32_t ahi[2][4], alo[2][4];
            {
                const uint32_t arow = warp_m * 32 + (lane & 15);
                const uint32_t acol = kk * 16 + (lane >> 4) * 8;
                const uint32_t off  = arow * ROWB + acol * 2;
                ldsm_x4(ahi[0], base + off);
                ldsm_x4(ahi[1], base + off + 16 * ROWB);
                ldsm_x4(alo[0], base + GA_BYTES + off);
                ldsm_x4(alo[1], base + GA_BYTES + off + 16 * ROWB);
            }
            uint32_t bhi[4][4], blo[4][4];
            {
                const uint32_t brow = warp_n * 64 + (lane & 7) + ((lane & 16) >> 1);
                const uint32_t bcol = kk * 16 + ((lane >> 3) & 1) * 8;
                const uint32_t off  = brow * ROWB + bcol * 2;
                #pragma unroll
                for (int q = 0; q < 4; q++) {
                    ldsm_x4(bhi[q], base + 2 * GA_BYTES + off + q * 16 * ROWB);
                    ldsm_x4(blo[q], base + 2 * GA_BYTES + GB_BYTES + off
                                    + q * 16 * ROWB);
                }
            }
            #pragma unroll
            for (int mt = 0; mt < 2; mt++)
                #pragma unroll
                for (int nt = 0; nt < 8; nt++)
                    mma16816(acc[mt][nt], ahi[mt], &bhi[nt >> 1][(nt & 1) * 2]);
            #pragma unroll
            for (int mt = 0; mt < 2; mt++)
                #pragma unroll
                for (int nt = 0; nt < 8; nt++)
                    mma16816(acc[mt][nt], ahi[mt], &blo[nt >> 1][(nt & 1) * 2]);
            #pragma unroll
            for (int mt = 0; mt < 2; mt++)
                #pragma unroll
                for (int nt = 0; nt < 8; nt++)
                    mma16816(acc[mt][nt], alo[mt], &bhi[nt >> 1][(nt & 1) * 2]);
        }
    }
}

// ============================================================================
// Batched QKV projection GEMM: grid (8, 128, 3), 128 threads, 3 CTAs/SM.
// ============================================================================
__global__ void __launch_bounds__(128, 3)
gemm_qkv(__nv_bfloat16* __restrict__ Qhi, __nv_bfloat16* __restrict__ Qlo,
         __nv_bfloat16* __restrict__ Khi, __nv_bfloat16* __restrict__ Klo,
         __nv_bfloat16* __restrict__ Vhi, __nv_bfloat16* __restrict__ Vlo)
{
    extern __shared__ char smem[];
    const uint32_t sb = smem_u32(smem);
    const int tid = threadIdx.x;
    const int bc = blockIdx.x, br = blockIdx.y, z = blockIdx.z;

    __nv_bfloat16 *Chi, *Clo;
    float scale;
    if (z == 0)      { Chi = Qhi; Clo = Qlo; scale = 0.125f; }
    else if (z == 1) { Chi = Khi; Clo = Klo; scale = 1.0f; }
    else             { Chi = Vhi; Clo = Vlo; scale = 1.0f; }

    float acc[2][8][4];
    #pragma unroll
    for (int mt = 0; mt < 2; mt++)
        #pragma unroll
        for (int nt = 0; nt < 8; nt++)
            #pragma unroll
            for (int i = 0; i < 4; i++) acc[mt][nt][i] = 0.0f;

    gemm_core(g_Ahi[z], g_Alo[z], g_Whi[z], g_Wlo[z], sb, tid, bc, br, acc);

    const int lane = tid & 31, wid = tid >> 5;
    const int warp_m = wid >> 1, warp_n = wid & 1;
    #pragma unroll
    for (int mt = 0; mt < 2; mt++) {
        #pragma unroll
        for (int nt = 0; nt < 8; nt++) {
            const int row0 = br * 64 + warp_m * 32 + mt * 16 + (lane >> 2);
            const int col  = bc * 128 + warp_n * 64 + nt * 8 + (lane & 3) * 2;
            const int h = col >> 6, dd = col & 63;
            #pragma unroll
            for (int half = 0; half < 2; half++) {
                const int r = row0 + half * 8;
                const int b = r >> 11, s = r & 2047;
                const long off = ((((long)b * NHEADS + h) * S_LEN + s) * HDIM) + dd;
                uint32_t hi, lo;
                split2(acc[mt][nt][half * 2] * scale,
                       acc[mt][nt][half * 2 + 1] * scale, hi, lo);
                *(uint32_t*)(Chi + off) = hi;
                *(uint32_t*)(Clo + off) = lo;
            }
        }
    }
}

// ============================================================================
// Output projection GEMM: fp32 row-major result. grid (8, 128), 128 threads.
// ============================================================================
__global__ void __launch_bounds__(128, 3)
gemm_out(const __nv_bfloat16* __restrict__ Ahi, const __nv_bfloat16* __restrict__ Alo,
         const __nv_bfloat16* __restrict__ Bhi, const __nv_bfloat16* __restrict__ Blo,
         float* __restrict__ Cf)
{
    extern __shared__ char smem[];
    const uint32_t sb = smem_u32(smem);
    const int tid = threadIdx.x;
    const int bc = blockIdx.x, br = blockIdx.y;

    float acc[2][8][4];
    #pragma unroll
    for (int mt = 0; mt < 2; mt++)
        #pragma unroll
        for (int nt = 0; nt < 8; nt++)
            #pragma unroll
            for (int i = 0; i < 4; i++) acc[mt][nt][i] = 0.0f;

    gemm_core(Ahi, Alo, Bhi, Blo, sb, tid, bc, br, acc);

    const int lane = tid & 31, wid = tid >> 5;
    const int warp_m = wid >> 1, warp_n = wid & 1;
    #pragma unroll
    for (int mt = 0; mt < 2; mt++) {
        #pragma unroll
        for (int nt = 0; nt < 8; nt++) {
            const int row0 = br * 64 + warp_m * 32 + mt * 16 + (lane >> 2);
            const int col  = bc * 128 + warp_n * 64 + nt * 8 + (lane & 3) * 2;
            float2 v01; v01.x = acc[mt][nt][0]; v01.y = acc[mt][nt][1];
            float2 v23; v23.x = acc[mt][nt][2]; v23.y = acc[mt][nt][3];
            *(float2*)&Cf[(long)row0 * DMODEL + col] = v01;
            *(float2*)&Cf[(long)(row0 + 8) * DMODEL + col] = v23;
        }
    }
}

// ============================================================================
// Tensor-core causal flash attention. 128 threads (4 warps x m16 = 64 q-rows).
// K ring 2-stage + V ring 2-stage; Q staged through V-stage-1 then overwritten.
// smem 73.7KB -> 3 CTAs/SM. grid (32, 64); q-blocks issued longest-first.
// ============================================================================
#define AROWB    144
#define ARR      (64 * AROWB)            // 9216   one array (64 rows)
#define KSTG     (2 * ARR)               // 18432  one K stage (hi+lo)
#define VOFF     (2 * KSTG)              // 36864  V ring base
#define ASMEM    (VOFF + 2 * KSTG)       // 73728

__global__ void __launch_bounds__(128, 3)
attn_mma(const __nv_bfloat16* __restrict__ Qhi, const __nv_bfloat16* __restrict__ Qlo,
         const __nv_bfloat16* __restrict__ Khi, const __nv_bfloat16* __restrict__ Klo,
         const __nv_bfloat16* __restrict__ Vhi, const __nv_bfloat16* __restrict__ Vlo,
         __nv_bfloat16* __restrict__ Ohi, __nv_bfloat16* __restrict__ Olo)
{
    extern __shared__ char smem[];
    const uint32_t sb = smem_u32(smem);
    const int tid = threadIdx.x, wid = tid >> 5, lane = tid & 31;
    const int qblk = (int)gridDim.x - 1 - (int)blockIdx.x;   // longest first
    const int q0 = qblk * 64;
    const int bh = blockIdx.y;
    const long base = (long)bh * S_LEN * HDIM;
    const int ntiles = qblk + 1;

    // group loaders: 1024 16B-chunks each, 8 per thread
    auto ld2arr = [&](const __nv_bfloat16* hi, const __nv_bfloat16* lo,
                      long grow0, uint32_t smem_base) {
        #pragma unroll
        for (int t = 0; t < 8; t++) {
            const int c = tid + t * 128;            // 0..1023
            const int arr = c >> 9, rem = c & 511;
            const int row = rem >> 3, seg = rem & 7;
            const __nv_bfloat16* src = (arr ? lo : hi)
                                     + base + (grow0 + row) * HDIM + seg * 8;
            cp_async16(smem_base + arr * ARR + row * AROWB + seg * 16, src);
        }
        cp_commit();
    };

    // ---- prologue ----
    ld2arr(Qhi, Qlo, (long)q0, sb + VOFF + KSTG);           // GQ -> V stage 1
    ld2arr(Khi, Klo, 0L, sb);                               // K(0) -> K stage 0
    cp_wait<1>();                                           // GQ done
    __syncthreads();

    uint32_t qhF[4][4], qlF[4][4];
    {
        const uint32_t arow = wid * 16 + (lane & 15);
        #pragma unroll
        for (int kt = 0; kt < 4; kt++) {
            const uint32_t off = arow * AROWB + (kt * 16 + (lane >> 4) * 8) * 2;
            ldsm_x4(qhF[kt], sb + VOFF + KSTG + off);
            ldsm_x4(qlF[kt], sb + VOFF + KSTG + ARR + off);
        }
    }
    __syncthreads();                                        // Q reads done
    ld2arr(Vhi, Vlo, 0L, sb + VOFF);                        // GV_{-1}: V(0)
    {
        const int tk = (1 < ntiles) ? 1 : 0;
        ld2arr(Khi, Klo, (long)tk * 64, sb + KSTG);         // GK_{-1}: K(1)
    }

    float m_s[2] = {-1e30f, -1e30f};
    float l_s[2] = {0.0f, 0.0f};
    float acc_o[8][4];
    #pragma unroll
    for (int nt = 0; nt < 8; nt++)
        #pragma unroll
        for (int i = 0; i < 4; i++) acc_o[nt][i] = 0.0f;

    const int wrow_lo = q0 + wid * 16;

    for (int t = 0; t < ntiles; t++) {
        cp_wait<2>();                 // K(t) resident
        __syncthreads();              // sync1: K(t) visible; V stage (t+1)&1 free
        {
            const int tv = (t + 1 < ntiles) ? t + 1 : ntiles - 1;
            ld2arr(Vhi, Vlo, (long)tv * 64, sb + VOFF + ((t + 1) & 1) * KSTG);
        }

        const uint32_t kbase = sb + (t & 1) * KSTG;
        const uint32_t vbase = sb + VOFF + (t & 1) * KSTG;
        const bool act = (t * 64 <= wrow_lo + 15);

        float acc_s[8][4];
        float tmax[2] = {-1e30f, -1e30f};
        bool act2 = false;

        if (act) {
            #pragma unroll
            for (int nt = 0; nt < 8; nt++)
                #pragma unroll
                for (int i = 0; i < 4; i++) acc_s[nt][i] = 0.0f;

            #pragma unroll
            for (int kt = 0; kt < 4; kt++) {
                uint32_t kh[4][4], kl[4][4];
                const uint32_t brow = (lane & 7) + ((lane & 16) >> 1);
                const uint32_t bcol = kt * 16 + ((lane >> 3) & 1) * 8;
                #pragma unroll
                for (int g = 0; g < 4; g++) {
                    const uint32_t off = (g * 16 + brow) * AROWB + bcol * 2;
                    ldsm_x4(kh[g], kbase + off);
                    ldsm_x4(kl[g], kbase + ARR + off);
                }
                #pragma unroll
                for (int nt = 0; nt < 8; nt++)
                    mma16816(acc_s[nt], qhF[kt], &kh[nt >> 1][(nt & 1) * 2]);
                #pragma unroll
                for (int nt = 0; nt < 8; nt++)
                    mma16816(acc_s[nt], qhF[kt], &kl[nt >> 1][(nt & 1) * 2]);
                #pragma unroll
                for (int nt = 0; nt < 8; nt++)
                    mma16816(acc_s[nt], qlF[kt], &kh[nt >> 1][(nt & 1) * 2]);
            }

            const int r0 = q0 + wid * 16 + (lane >> 2);
            if (t * 64 + 63 > wrow_lo) {
                #pragma unroll
                for (int nt = 0; nt < 8; nt++)
                    #pragma unroll
                    for (int i = 0; i < 4; i++) {
                        const int row = r0 + (i >> 1) * 8;
                        const int col = t * 64 + nt * 8 + 2 * (lane & 3) + (i & 1);
                        if (col > row) acc_s[nt][i] = -1e30f;
                    }
            }

            #pragma unroll
            for (int nt = 0; nt < 8; nt++)
                #pragma unroll
                for (int i = 0; i < 4; i++)
                    tmax[i >> 1] = fmaxf(tmax[i >> 1], acc_s[nt][i]);
            #pragma unroll
            for (int h = 0; h < 2; h++) {
                tmax[h] = fmaxf(tmax[h], __shfl_xor_sync(0xffffffffu, tmax[h], 1));
                tmax[h] = fmaxf(tmax[h], __shfl_xor_sync(0xffffffffu, tmax[h], 2));
            }
            float d = fmaxf(tmax[0] - m_s[0], tmax[1] - m_s[1]);
            d = fmaxf(d, __shfl_xor_sync(0xffffffffu, d, 4));
            d = fmaxf(d, __shfl_xor_sync(0xffffffffu, d, 8));
            d = fmaxf(d, __shfl_xor_sync(0xffffffffu, d, 16));
            act2 = (d >= -44.0f);
        }

        cp_wait<2>();                 // V(t) resident
        __syncthreads();              // sync2: V(t) visible; K stage t&1 reads done
        {
            const int tk = (t + 2 < ntiles) ? t + 2 : ntiles - 1;
            ld2arr(Khi, Klo, (long)tk * 64, sb + (t & 1) * KSTG);
        }

        if (act && act2) {
            float nm[2], corr[2];
            #pragma unroll
            for (int h = 0; h < 2; h++) {
                nm[h]   = fmaxf(m_s[h], tmax[h]);
                corr[h] = __expf(m_s[h] - nm[h]);
                m_s[h]  = nm[h];
            }
            float psum[2] = {0.0f, 0.0f};
            #pragma unroll
            for (int nt = 0; nt < 8; nt++)
                #pragma unroll
                for (int i = 0; i < 4; i++) {
                    const float p = __expf(acc_s[nt][i] - nm[i >> 1]);
                    acc_s[nt][i] = p;
                    psum[i >> 1] += p;
                }
            #pragma unroll
            for (int h = 0; h < 2; h++) {
                psum[h] += __shfl_xor_sync(0xffffffffu, psum[h], 1);
                psum[h] += __shfl_xor_sync(0xffffffffu, psum[h], 2);
                l_s[h] = l_s[h] * corr[h] + psum[h];
            }
            #pragma unroll
            for (int nt = 0; nt < 8; nt++)
                #pragma unroll
                for (int i = 0; i < 4; i++) acc_o[nt][i] *= corr[i >> 1];

            uint32_t ph[4][4], pl[4][4];
            #pragma unroll
            for (int kt = 0; kt < 4; kt++) {
                split2(acc_s[2 * kt][0],     acc_s[2 * kt][1],     ph[kt][0], pl[kt][0]);
                split2(acc_s[2 * kt][2],     acc_s[2 * kt][3],     ph[kt][1], pl[kt][1]);
                split2(acc_s[2 * kt + 1][0], acc_s[2 * kt + 1][1], ph[kt][2], pl[kt][2]);
                split2(acc_s[2 * kt + 1][2], acc_s[2 * kt + 1][3], ph[kt][3], pl[kt][3]);
            }

            #pragma unroll
            for (int kt = 0; kt < 4; kt++) {
                uint32_t vh[4][4], vl[4][4];
                const uint32_t vrow = kt * 16 + (lane & 15);
                const uint32_t vcol = (lane >> 4) * 8;
                #pragma unroll
                for (int g = 0; g < 4; g++) {
                    const uint32_t off = vrow * AROWB + (g * 16 + vcol) * 2;
                    ldsm_x4t(vh[g], vbase + off);
                    ldsm_x4t(vl[g], vbase + ARR + off);
                }
                #pragma unroll
                for (int nt = 0; nt < 8; nt++)
                    mma16816(acc_o[nt], ph[kt], &vh[nt >> 1][(nt & 1) * 2]);
                #pragma unroll
                for (int nt = 0; nt < 8; nt++)
                    mma16816(acc_o[nt], pl[kt], &vh[nt >> 1][(nt & 1) * 2]);
                #pragma unroll
                for (int nt = 0; nt < 8; nt++)
                    mma16816(acc_o[nt], ph[kt], &vl[nt >> 1][(nt & 1) * 2]);
            }
        }
    }

    // ---- epilogue ----
    const float inv0 = 1.0f / l_s[0];
    const float inv1 = 1.0f / l_s[1];
    const int b  = bh >> 4;
    const int hh = bh & 15;
    const int r0 = q0 + wid * 16 + (lane >> 2);
    #pragma unroll
    for (int nt = 0; nt < 8; nt++) {
        const int col = hh * 64 + nt * 8 + 2 * (lane & 3);
        {
            const long idx = ((long)(b * S_LEN + r0)) * DMODEL + col;
            uint32_t hi, lo;
            split2(acc_o[nt][0] * inv0, acc_o[nt][1] * inv0, hi, lo);
            *(uint32_t*)(Ohi + idx) = hi;
            *(uint32_t*)(Olo + idx) = lo;
        }
        {
            const long idx = ((long)(b * S_LEN + r0 + 8)) * DMODEL + col;
            uint32_t hi, lo;
            split2(acc_o[nt][2] * inv1, acc_o[nt][3] * inv1, hi, lo);
            *(uint32_t*)(Ohi + idx) = hi;
            *(uint32_t*)(Olo + idx) = lo;
        }
    }
}

// ============================================================================
// conversion kernels (fused)
// ============================================================================
__global__ void __launch_bounds__(256)
conv_qkv(const float* __restrict__ q, const float* __restrict__ k,
         const float* __restrict__ v)
{
    const int z = blockIdx.y;
    const float* X = (z == 0) ? q : (z == 1) ? k : v;
    const int i = blockIdx.x * 256 + threadIdx.x;   // over float2
    const float2 x = ((const float2*)X)[i];
    uint32_t h, l;
    split2(x.x, x.y, h, l);
    ((uint32_t*)g_Ahi[z])[i] = h;
    ((uint32_t*)g_Alo[z])[i] = l;
}

__global__ void __launch_bounds__(256)
conv_w(const float* __restrict__ W0, const float* __restrict__ W1,
       const float* __restrict__ W2, const float* __restrict__ W3)
{
    __shared__ float t[32][33];
    const int z = blockIdx.z;
    const float* W = (z == 0) ? W0 : (z == 1) ? W1 : (z == 2) ? W2 : W3;
    const int tx = threadIdx.x, ty = threadIdx.y;     // (32, 8)
    const int n0 = blockIdx.x * 32, k0 = blockIdx.y * 32;
    #pragma unroll
    for (int r = 0; r < 4; r++) {
        const int k = ty + r * 8;
        t[k][tx] = W[(long)(k0 + k) * DMODEL + n0 + tx];
    }
    __syncthreads();
    #pragma unroll
    for (int r = 0; r < 4; r++) {
        const int nl = ty + r * 8;
        const float x = t[tx][nl];
        const __nv_bfloat16 h = __float2bfloat16(x);
        const long o = (long)(n0 + nl) * DMODEL + k0 + tx;
        g_Whi[z][o] = h;
        g_Wlo[z][o] = __float2bfloat16(x - __bfloat162float(h));
    }
}

// ============================================================================
extern "C" void kernel_launch(void* const* d_in, const int* in_sizes, int n_in,
                              void* d_out, int out_size)
{
    const float* q = (const float*)d_in[0];
    const float* k = (const float*)d_in[1];
    const float* v = (const float*)d_in[2];
    float* out = (float*)d_out;

    __nv_bfloat16 *whi, *wlo;
    __nv_bfloat16 *qhi, *qlo, *khi, *klo, *vhi, *vlo, *ohi, *olo;
    cudaGetSymbolAddress((void**)&whi, g_Whi);
    cudaGetSymbolAddress((void**)&wlo, g_Wlo);
    cudaGetSymbolAddress((void**)&qhi, g_Qhi);
    cudaGetSymbolAddress((void**)&qlo, g_Qlo);
    cudaGetSymbolAddress((void**)&khi, g_Khi);
    cudaGetSymbolAddress((void**)&klo, g_Klo);
    cudaGetSymbolAddress((void**)&vhi, g_Vhi);
    cudaGetSymbolAddress((void**)&vlo, g_Vlo);
    cudaGetSymbolAddress((void**)&ohi, g_Ohi);
    cudaGetSymbolAddress((void**)&olo, g_Olo);

    cudaFuncSetAttribute((const void*)gemm_qkv,
                         cudaFuncAttributeMaxDynamicSharedMemorySize, GSMEM);
    cudaFuncSetAttribute((const void*)gemm_out,
                         cudaFuncAttributeMaxDynamicSharedMemorySize, GSMEM);
    cudaFuncSetAttribute((const void*)attn_mma,
                         cudaFuncAttributeMaxDynamicSharedMemorySize, ASMEM);

    conv_w<<<dim3(32, 32, 4), dim3(32, 8)>>>(
        (const float*)d_in[3], (const float*)d_in[4],
        (const float*)d_in[5], (const float*)d_in[6]);

    conv_qkv<<<dim3(AELEMS / 2 / 256, 3), 256>>>(q, k, v);

    gemm_qkv<<<dim3(8, 128, 3), 128, GSMEM>>>(qhi, qlo, khi, klo, vhi, vlo);

    attn_mma<<<dim3(S_LEN / 64, BHCNT), 128, ASMEM>>>(qhi, qlo, khi, klo,
                                                      vhi, vlo, ohi, olo);

    gemm_out<<<dim3(8, 128), 128, GSMEM>>>(ohi, olo,
        whi + 3 * (long)WELEMS, wlo + 3 * (long)WELEMS, out);
}